// round 14
// baseline (speedup 1.0000x reference)
#include <cuda_runtime.h>
#include <cuda_bf16.h>
#include <math.h>
#include <stdint.h>

#define BB  8
#define NN  128
#define XD_ 256
#define ED_ 128
#define FFX 1024
#define FFE 512
#define ROWS_X (BB*NN)
#define ROWS_E (BB*NN*NN)
#define INV_SQRT_DF 0.17677669529663687f

#define PITCH   272           // bytes per bf16 tile row (136 bf16)
#define TILE_W  34816         // 128 * 272 (one bf16 128x128 weight tile)

// ---------------- scratch ----------------
__device__ float g_Q   [ROWS_X * XD_];
__device__ float g_Km  [ROWS_X * XD_];
__device__ float g_newX[ROWS_X * XD_];
__device__ float g_hx  [ROWS_X * XD_];
__device__ float g_h1x [ROWS_X * FFX];
__device__ float g_h2x [ROWS_X * XD_];
__device__ float g_wvx [XD_ * XD_];
__device__ float g_bvx [XD_];
__device__ float g_zero[FFX];
__device__ float g_w2  [ED_ * ED_];      // wea @ weo (fp32)
__device__ float g_beoF[ED_];            // beo + bea @ weo
__device__ __align__(16) char g_wemP[2 * TILE_W];
__device__ __align__(16) char g_weoP[2 * TILE_W];
__device__ __align__(16) char g_w2P [TILE_W];
__device__ __align__(16) char g_we1P[4 * TILE_W];
__device__ __align__(16) char g_we2P[4 * TILE_W];

// ---------------- helpers ----------------
__device__ __forceinline__ uint32_t smem_u32(const void* p) {
    uint32_t a;
    asm("{ .reg .u64 t; cvta.to.shared.u64 t, %1; cvt.u32.u64 %0, t; }" : "=r"(a) : "l"(p));
    return a;
}

#define CPA16(dst, src) asm volatile("cp.async.cg.shared.global [%0], [%1], 16;" :: "r"(dst), "l"(src))
#define CP_COMMIT() asm volatile("cp.async.commit_group;" ::: "memory")
#define CP_WAIT0()  asm volatile("cp.async.wait_group 0;" ::: "memory")

#define EDGE_T 128   // threads per edge CTA

__device__ __forceinline__ void prefetch_w(uint32_t dstS, const char* src, int tid) {
    #pragma unroll 4
    for (int t = tid; t < 2176; t += EDGE_T)
        CPA16(dstS + (uint32_t)t * 16, src + (size_t)t * 16);
    CP_COMMIT();
}

__device__ __forceinline__ void mma16816(float* c, uint32_t a0, uint32_t a1, uint32_t a2,
                                         uint32_t a3, uint32_t b0, uint32_t b1) {
    asm volatile(
        "mma.sync.aligned.m16n8k16.row.col.f32.bf16.bf16.f32 "
        "{%0,%1,%2,%3},{%4,%5,%6,%7},{%8,%9},{%0,%1,%2,%3};"
        : "+f"(c[0]), "+f"(c[1]), "+f"(c[2]), "+f"(c[3])
        : "r"(a0), "r"(a1), "r"(a2), "r"(a3), "r"(b0), "r"(b1));
}

__device__ __forceinline__ void ldsm4(uint32_t& r0, uint32_t& r1, uint32_t& r2, uint32_t& r3,
                                      uint32_t a) {
    asm volatile("ldmatrix.sync.aligned.m8n8.x4.shared.b16 {%0,%1,%2,%3},[%4];"
                 : "=r"(r0), "=r"(r1), "=r"(r2), "=r"(r3) : "r"(a));
}

// A fragment: 32 rows x 16 k
__device__ __forceinline__ void ldA8(uint32_t a[8], uint32_t base, int r0, int k0, int lane) {
    uint32_t addr = base + (uint32_t)(r0 + (lane & 15)) * PITCH
                  + (uint32_t)(k0 + ((lane >> 4) << 3)) * 2;
    ldsm4(a[0], a[1], a[2], a[3], addr);
    ldsm4(a[4], a[5], a[6], a[7], addr + 16 * PITCH);
}

// B fragment: 64 n x 16 k
__device__ __forceinline__ void ldB16(uint32_t b[16], uint32_t base, int n0, int k0, int lane) {
    uint32_t addr = base + (uint32_t)(n0 + ((lane >> 4) << 3) + (lane & 7)) * PITCH
                  + (uint32_t)(k0 + (((lane >> 3) & 1) << 3)) * 2;
    ldsm4(b[0],  b[1],  b[2],  b[3],  addr);
    ldsm4(b[4],  b[5],  b[6],  b[7],  addr + 16 * PITCH);
    ldsm4(b[8],  b[9],  b[10], b[11], addr + 32 * PITCH);
    ldsm4(b[12], b[13], b[14], b[15], addr + 48 * PITCH);
}

__device__ __forceinline__ void mma_pass(float (&acc)[2][8][4], const uint32_t a[8],
                                         const uint32_t b[16]) {
    #pragma unroll
    for (int mf = 0; mf < 2; mf++)
        #pragma unroll
        for (int nf = 0; nf < 8; nf++)
            mma16816(acc[mf][nf], a[mf*4], a[mf*4+1], a[mf*4+2], a[mf*4+3],
                     b[nf*2], b[nf*2+1]);
}

// 1-pass bf16 GEMM tile (local M=64 across 2 m-warps, N=128 across 2 n-warps, K=128)
__device__ __forceinline__ void compute_ktile(float (&acc)[2][8][4], uint32_t aB,
                                              uint32_t bB, int wm, int wn, int lane) {
    #pragma unroll 2
    for (int ks = 0; ks < 8; ks++) {
        uint32_t ah[8], bh[16];
        ldA8(ah, aB, wm * 32, ks * 16, lane);
        ldB16(bh, bB, wn * 64, ks * 16, lane);
        mma_pass(acc, ah, bh);
    }
}

__device__ __forceinline__ uint32_t pkf2(float x, float y) {
    __nv_bfloat162 t = __floats2bfloat162_rn(x, y);
    return *reinterpret_cast<uint32_t*>(&t);
}

// stage 64x128 fp32 -> bf16 pitched tile (128 threads)
__device__ __forceinline__ void stage_a_fp32(char* sm, const float* src, int stride, int tid) {
    #pragma unroll 4
    for (int t = tid; t < 2048; t += EDGE_T) {
        int r = t >> 5, c4 = (t & 31) << 2;
        float4 v = *(const float4*)(src + (size_t)r * stride + c4);
        uint32_t p0 = pkf2(v.x, v.y);
        uint32_t p1 = pkf2(v.z, v.w);
        *(uint2*)(sm + (uint32_t)r * PITCH + (uint32_t)c4 * 2) = make_uint2(p0, p1);
    }
}

// ---------------- weight prep ----------------
__device__ __forceinline__ void prep_tile(const float* W, char* out, int N, int kc, int nc,
                                          float* tl, int tid) {
    for (int t = tid; t < 16384; t += 256) {
        int k = t >> 7, n = t & 127;
        tl[k * 129 + n] = W[(size_t)(kc * 128 + k) * N + nc * 128 + n];
    }
    __syncthreads();
    for (int t = tid; t < 8192; t += 256) {
        int n = t >> 6, k = (t & 63) << 1;
        float v0 = tl[k * 129 + n], v1 = tl[(k + 1) * 129 + n];
        *(uint32_t*)(out + (uint32_t)n * PITCH + (uint32_t)k * 2) = pkf2(v0, v1);
    }
}

__global__ void prep_all12(const float* __restrict__ wem, const float* __restrict__ weo,
                           const float* __restrict__ we1, const float* __restrict__ we2,
                           char* __restrict__ wemP, char* __restrict__ weoP,
                           char* __restrict__ we1P, char* __restrict__ we2P)
{
    extern __shared__ float tl[];   // 128 x 129
    int s = blockIdx.x;
    const float* W; char* out; int N, kc, nc;
    if (s < 2)       { W = wem; out = wemP + (size_t)s       * TILE_W; N = 256; kc = 0;     nc = s;     }
    else if (s < 4)  { W = weo; out = weoP + (size_t)(s - 2) * TILE_W; N = 128; kc = s - 2; nc = 0;     }
    else if (s < 8)  { W = we1; out = we1P + (size_t)(s - 4) * TILE_W; N = 512; kc = 0;     nc = s - 4; }
    else             { W = we2; out = we2P + (size_t)(s - 8) * TILE_W; N = 128; kc = s - 8; nc = 0;     }
    prep_tile(W, out, N, kc, nc, tl, threadIdx.x);
}

__global__ void prep_w2(const float* __restrict__ w2, char* __restrict__ w2P) {
    extern __shared__ float tl[];
    prep_tile(w2, w2P, 128, 0, 0, tl, threadIdx.x);
}

__global__ void fold_bias(const float* __restrict__ bv, const float* __restrict__ wxo,
                          const float* __restrict__ bxo, float* __restrict__ bvx) {
    int n = threadIdx.x;
    float s = bxo[n];
    for (int k = 0; k < XD_; ++k) s += bv[k] * wxo[k * XD_ + n];
    bvx[n] = s;
}

__global__ void fold_beo(const float* __restrict__ bea, const float* __restrict__ weo,
                         const float* __restrict__ beo, float* __restrict__ beoF) {
    int n = threadIdx.x;
    float s = beo[n];
    for (int c = 0; c < XD_; ++c) s += bea[c] * weo[c * ED_ + n];
    beoF[n] = s;
}

// ================ fused edge kernel: 64-row tiles, 128 threads, 2 CTAs/SM ================
#define R_A   0          // 17408
#define R_B0  17408      // 34816
#define R_B1  52224      // 34816
#define R_C   87040      // 17408
#define R_SM  104448
#define EF_BYTES (104448 + 8192)

__global__ void __launch_bounds__(EDGE_T, 2) edge_fused_kernel(
    const float* __restrict__ e, const float* __restrict__ Qs, const float* __restrict__ Km,
    const char* __restrict__ w2P, const char* __restrict__ wemP, const char* __restrict__ weoP,
    const char* __restrict__ we1P, const char* __restrict__ we2P,
    const float* __restrict__ bem, const float* __restrict__ beoF,
    const float* __restrict__ be1, const float* __restrict__ be2,
    const float* __restrict__ gne, const float* __restrict__ bne,
    float* __restrict__ e_out)
{
    extern __shared__ char sm[];
    const int tid = threadIdx.x;
    const int lane = tid & 31, w = tid >> 5;
    const int wm = w & 1, wn = w >> 1;      // 2(M) x 2(N) warp grid
    const int g = lane >> 2, q = lane & 3;
    const int blk = blockIdx.x;
    const size_t row0 = (size_t)blk * 64;
    const int b = (int)(row0 >> 14);
    const int i = (int)((row0 >> 7) & 127);
    const int j0 = (int)(row0 & 127);       // 0 or 64

    uint32_t smB = smem_u32(sm);
    float* qS   = (float*)(sm + R_SM);              // 256
    float* bemS = qS + 256;                          // 256
    float* beoS = bemS + 256;                        // 128
    float* gneS = beoS + 128;                        // 128
    float* bneS = gneS + 128;                        // 128
    float* be1S = bneS + 128;                        // 512
    float* be2S = be1S + 512;                        // 128
    float* red  = be2S + 128;                        // 128
    float* red2 = red + 128;                         // 128

    const uint32_t aB = smB + R_A;
    const uint32_t cB = smB + R_C;
    const uint32_t Bb[2] = {smB + R_B0, smB + R_B1};
    const char* tiles[13] = {
        w2P, wemP, weoP, wemP + TILE_W, weoP + TILE_W,
        we1P,              we2P,
        we1P + TILE_W,     we2P + TILE_W,
        we1P + 2 * TILE_W, we2P + 2 * TILE_W,
        we1P + 3 * TILE_W, we2P + 3 * TILE_W};

    prefetch_w(Bb[0], tiles[0], tid);               // tile 0 in flight
    stage_a_fp32(sm + R_A, e + row0 * ED_, ED_, tid);
    #pragma unroll
    for (int t = tid; t < 256; t += EDGE_T) {
        qS[t]   = Qs[((size_t)(b * NN + i)) * XD_ + t];
        bemS[t] = bem[t];
    }
    beoS[tid] = beoF[tid];
    gneS[tid] = gne[tid];
    bneS[tid] = bne[tid];
    be2S[tid] = be2[tid];
    #pragma unroll
    for (int t = tid; t < 512; t += EDGE_T) be1S[t] = be1[t];
    CP_WAIT0(); __syncthreads();
    prefetch_w(Bb[1], tiles[1], tid);               // tile 1 in flight

    // =================== attention phase ===================
    float accNE[2][8][4] = {};

    // ---- phase 0: accNE = e @ W2   (collapsed E2 path)
    compute_ktile(accNE, aB, Bb[0], wm, wn, lane);
    CP_WAIT0(); __syncthreads();
    prefetch_w(Bb[0], tiles[2], tid);

    #pragma unroll 1
    for (int nc = 0; nc < 2; nc++) {
        const int p = 1 + nc * 2;
        // ---- phase p (wem[nc]): E1 = e@wem; Y = q*km*(E1+bem+1) -> bf16 into C
        {
            float acc[2][8][4] = {};
            compute_ktile(acc, aB, Bb[p & 1], wm, wn, lane);
            #pragma unroll
            for (int mf = 0; mf < 2; mf++)
            #pragma unroll
            for (int h = 0; h < 2; h++) {
                int r = wm * 32 + mf * 16 + h * 8 + g;
                const float* kp = Km + ((size_t)(b * NN + j0 + r)) * XD_ + nc * 128;
                #pragma unroll
                for (int nf = 0; nf < 8; nf++) {
                    int cl = wn * 64 + nf * 8 + q * 2;
                    int cg = nc * 128 + cl;
                    float2 km = *(const float2*)(kp + cl);
                    float y0 = qS[cg]   * km.x * (acc[mf][nf][h*2]   + bemS[cg]   + 1.f);
                    float y1 = qS[cg+1] * km.y * (acc[mf][nf][h*2+1] + bemS[cg+1] + 1.f);
                    *(uint32_t*)(sm + R_C + (uint32_t)r * PITCH + (uint32_t)cl * 2) = pkf2(y0, y1);
                }
            }
        }
        CP_WAIT0(); __syncthreads();
        prefetch_w(Bb[p & 1], tiles[p + 2], tid);
        // ---- phase p+1 (weo[nc]): accNE += Y @ weo
        compute_ktile(accNE, cB, Bb[(p + 1) & 1], wm, wn, lane);
        CP_WAIT0(); __syncthreads();
        prefetch_w(Bb[(p + 1) & 1], tiles[p + 3], tid);
    }

    // ---- attn epilogue: he = LN(e + accNE + beoF)*gne + bne -> bf16 INTO A REGION
    #pragma unroll
    for (int mf = 0; mf < 2; mf++)
    #pragma unroll
    for (int h = 0; h < 2; h++) {
        int r = wm * 32 + mf * 16 + h * 8 + g;
        #pragma unroll
        for (int nf = 0; nf < 8; nf++) {
            int cl = wn * 64 + nf * 8 + q * 2;
            float2 ev = *(const float2*)(e + (row0 + r) * ED_ + cl);
            accNE[mf][nf][h*2+0] += beoS[cl]   + ev.x;
            accNE[mf][nf][h*2+1] += beoS[cl+1] + ev.y;
        }
    }
    {
        float mean[2][2], rstd[2][2];
        #pragma unroll
        for (int mf = 0; mf < 2; mf++)
        #pragma unroll
        for (int h = 0; h < 2; h++) {
            float s = 0.f;
            #pragma unroll
            for (int nf = 0; nf < 8; nf++) s += accNE[mf][nf][h*2] + accNE[mf][nf][h*2+1];
            s += __shfl_xor_sync(0xffffffffu, s, 1);
            s += __shfl_xor_sync(0xffffffffu, s, 2);
            if (q == 0) red[wn * 64 + wm * 32 + mf * 16 + h * 8 + g] = s;
        }
        __syncthreads();
        #pragma unroll
        for (int mf = 0; mf < 2; mf++)
        #pragma unroll
        for (int h = 0; h < 2; h++) {
            int r = wm * 32 + mf * 16 + h * 8 + g;
            mean[mf][h] = (red[r] + red[64 + r]) * (1.f / 128.f);
            float s = 0.f;
            #pragma unroll
            for (int nf = 0; nf < 8; nf++) {
                float d0 = accNE[mf][nf][h*2]   - mean[mf][h];
                float d1 = accNE[mf][nf][h*2+1] - mean[mf][h];
                s += d0 * d0 + d1 * d1;
            }
            s += __shfl_xor_sync(0xffffffffu, s, 1);
            s += __shfl_xor_sync(0xffffffffu, s, 2);
            if (q == 0) red2[wn * 64 + r] = s;
        }
        __syncthreads();
        #pragma unroll
        for (int mf = 0; mf < 2; mf++)
        #pragma unroll
        for (int h = 0; h < 2; h++) {
            int r = wm * 32 + mf * 16 + h * 8 + g;
            rstd[mf][h] = rsqrtf((red2[r] + red2[64 + r]) * (1.f / 128.f) + 1e-5f);
            #pragma unroll
            for (int nf = 0; nf < 8; nf++) {
                int cl = wn * 64 + nf * 8 + q * 2;
                float o0 = (accNE[mf][nf][h*2]   - mean[mf][h]) * rstd[mf][h] * gneS[cl]   + bneS[cl];
                float o1 = (accNE[mf][nf][h*2+1] - mean[mf][h]) * rstd[mf][h] * gneS[cl+1] + bneS[cl+1];
                // he -> A region, MMA layout (e-tile is dead now)
                *(uint32_t*)(sm + R_A + (uint32_t)r * PITCH + (uint32_t)cl * 2) = pkf2(o0, o1);
            }
        }
    }
    __syncthreads();   // he visible to all warps before FF ktiles

    // =================== FF phase (A = he, C = h1 chunks) ===================
    float accH2[2][8][4] = {};

    #pragma unroll 1
    for (int p = 0; p < 4; p++) {
        const int i0 = 5 + p * 2;
        // ---- tile i0 (we1[p]): h1 = relu(he@we1 + be1) -> bf16 into C
        {
            float acc[2][8][4] = {};
            compute_ktile(acc, aB, Bb[i0 & 1], wm, wn, lane);
            #pragma unroll
            for (int mf = 0; mf < 2; mf++)
            #pragma unroll
            for (int h = 0; h < 2; h++) {
                int r = wm * 32 + mf * 16 + h * 8 + g;
                #pragma unroll
                for (int nf = 0; nf < 8; nf++) {
                    int cl = wn * 64 + nf * 8 + q * 2;
                    int cgl = p * 128 + cl;
                    float o0 = fmaxf(acc[mf][nf][h*2]   + be1S[cgl],   0.f);
                    float o1 = fmaxf(acc[mf][nf][h*2+1] + be1S[cgl+1], 0.f);
                    *(uint32_t*)(sm + R_C + (uint32_t)r * PITCH + (uint32_t)cl * 2) = pkf2(o0, o1);
                }
            }
        }
        CP_WAIT0(); __syncthreads();
        if (i0 + 2 < 13) prefetch_w(Bb[i0 & 1], tiles[i0 + 2], tid);
        // ---- tile i0+1 (we2[p]): h2 += h1chunk @ we2
        compute_ktile(accH2, cB, Bb[(i0 + 1) & 1], wm, wn, lane);
        CP_WAIT0(); __syncthreads();
        if (i0 + 3 < 13) prefetch_w(Bb[(i0 + 1) & 1], tiles[i0 + 3], tid);
    }

    // ---- FF epilogue: e_out = LN(e + h2 + be2) * gne + bne
    #pragma unroll
    for (int mf = 0; mf < 2; mf++)
    #pragma unroll
    for (int h = 0; h < 2; h++) {
        int r = wm * 32 + mf * 16 + h * 8 + g;
        #pragma unroll
        for (int nf = 0; nf < 8; nf++) {
            int cl = wn * 64 + nf * 8 + q * 2;
            float2 ev = *(const float2*)(e + (row0 + r) * ED_ + cl);
            accH2[mf][nf][h*2+0] += be2S[cl]   + ev.x;
            accH2[mf][nf][h*2+1] += be2S[cl+1] + ev.y;
        }
    }
    float mean[2][2], rstd[2][2];
    #pragma unroll
    for (int mf = 0; mf < 2; mf++)
    #pragma unroll
    for (int h = 0; h < 2; h++) {
        float s = 0.f;
        #pragma unroll
        for (int nf = 0; nf < 8; nf++) s += accH2[mf][nf][h*2] + accH2[mf][nf][h*2+1];
        s += __shfl_xor_sync(0xffffffffu, s, 1);
        s += __shfl_xor_sync(0xffffffffu, s, 2);
        if (q == 0) red[wn * 64 + wm * 32 + mf * 16 + h * 8 + g] = s;
    }
    __syncthreads();
    #pragma unroll
    for (int mf = 0; mf < 2; mf++)
    #pragma unroll
    for (int h = 0; h < 2; h++) {
        int r = wm * 32 + mf * 16 + h * 8 + g;
        mean[mf][h] = (red[r] + red[64 + r]) * (1.f / 128.f);
        float s = 0.f;
        #pragma unroll
        for (int nf = 0; nf < 8; nf++) {
            float d0 = accH2[mf][nf][h*2]   - mean[mf][h];
            float d1 = accH2[mf][nf][h*2+1] - mean[mf][h];
            s += d0 * d0 + d1 * d1;
        }
        s += __shfl_xor_sync(0xffffffffu, s, 1);
        s += __shfl_xor_sync(0xffffffffu, s, 2);
        if (q == 0) red2[wn * 64 + r] = s;
    }
    __syncthreads();
    #pragma unroll
    for (int mf = 0; mf < 2; mf++)
    #pragma unroll
    for (int h = 0; h < 2; h++) {
        int r = wm * 32 + mf * 16 + h * 8 + g;
        rstd[mf][h] = rsqrtf((red2[r] + red2[64 + r]) * (1.f / 128.f) + 1e-5f);
        #pragma unroll
        for (int nf = 0; nf < 8; nf++) {
            int cl = wn * 64 + nf * 8 + q * 2;
            float o0 = (accH2[mf][nf][h*2]   - mean[mf][h]) * rstd[mf][h] * gneS[cl]   + bneS[cl];
            float o1 = (accH2[mf][nf][h*2+1] - mean[mf][h]) * rstd[mf][h] * gneS[cl+1] + bneS[cl+1];
            *(float2*)(e_out + (row0 + r) * ED_ + cl) = make_float2(o0, o1);
        }
    }
}

// ---------------- node-side SIMT GEMM + LN ----------------
template<bool RELU>
__global__ void __launch_bounds__(256) gemm_kernel(
    const float* __restrict__ A, const float* __restrict__ W,
    const float* __restrict__ bias, float* __restrict__ C,
    int M, int N, int K, float alpha)
{
    __shared__ __align__(16) float aS[64][68];
    __shared__ __align__(16) float wS[64][68];
    const int tid = threadIdx.x;
    const int tx  = tid & 15;
    const int ty  = tid >> 4;
    const size_t row0 = (size_t)blockIdx.y * 64;
    const int    col0 = blockIdx.x * 64;
    float acc[4][4] = {};
    for (int k0 = 0; k0 < K; k0 += 64) {
        #pragma unroll
        for (int t = tid; t < 1024; t += 256) {
            int r = t >> 4, c4 = (t & 15) << 2;
            float4 av = *(const float4*)(A + (row0 + r) * K + k0 + c4);
            aS[r][c4+0]=av.x; aS[r][c4+1]=av.y; aS[r][c4+2]=av.z; aS[r][c4+3]=av.w;
            float4 wv = *(const float4*)(W + (size_t)(k0 + r) * N + col0 + c4);
            wS[r][c4+0]=wv.x; wS[r][c4+1]=wv.y; wS[r][c4+2]=wv.z; wS[r][c4+3]=wv.w;
        }
        __syncthreads();
        #pragma unroll 16
        for (int k = 0; k < 64; ++k) {
            float a0=aS[ty*4+0][k], a1=aS[ty*4+1][k], a2=aS[ty*4+2][k], a3=aS[ty*4+3][k];
            float4 bv = *(const float4*)&wS[k][tx*4];
            acc[0][0]+=a0*bv.x; acc[0][1]+=a0*bv.y; acc[0][2]+=a0*bv.z; acc[0][3]+=a0*bv.w;
            acc[1][0]+=a1*bv.x; acc[1][1]+=a1*bv.y; acc[1][2]+=a1*bv.z; acc[1][3]+=a1*bv.w;
            acc[2][0]+=a2*bv.x; acc[2][1]+=a2*bv.y; acc[2][2]+=a2*bv.z; acc[2][3]+=a2*bv.w;
            acc[3][0]+=a3*bv.x; acc[3][1]+=a3*bv.y; acc[3][2]+=a3*bv.z; acc[3][3]+=a3*bv.w;
        }
        __syncthreads();
    }
    const int c = col0 + tx * 4;
    float b0=bias[c+0], b1=bias[c+1], b2=bias[c+2], b3=bias[c+3];
    #pragma unroll
    for (int m = 0; m < 4; ++m) {
        float4 o;
        o.x = alpha*(acc[m][0]+b0); o.y = alpha*(acc[m][1]+b1);
        o.z = alpha*(acc[m][2]+b2); o.w = alpha*(acc[m][3]+b3);
        if (RELU) { o.x=fmaxf(o.x,0.f); o.y=fmaxf(o.y,0.f); o.z=fmaxf(o.z,0.f); o.w=fmaxf(o.w,0.f); }
        *(float4*)(C + (row0 + ty*4 + m) * N + c) = o;
    }
}

__global__ void ln_kernel(const float* __restrict__ A, const float* __restrict__ Bv,
                          const float* __restrict__ g, const float* __restrict__ be,
                          float* __restrict__ out)
{
    __shared__ float red[8];
    const int D = blockDim.x;
    const size_t base = (size_t)blockIdx.x * D + threadIdx.x;
    const int lane = threadIdx.x & 31;
    const int w    = threadIdx.x >> 5;
    const int nw   = D >> 5;
    float v = A[base] + Bv[base];
    float s = v;
    #pragma unroll
    for (int o = 16; o; o >>= 1) s += __shfl_xor_sync(0xffffffffu, s, o);
    if (lane == 0) red[w] = s;
    __syncthreads();
    float tot = 0.f;
    for (int ww = 0; ww < nw; ++ww) tot += red[ww];
    float mean = tot / (float)D;
    float d = v - mean;
    __syncthreads();
    float s2 = d * d;
    #pragma unroll
    for (int o = 16; o; o >>= 1) s2 += __shfl_xor_sync(0xffffffffu, s2, o);
    if (lane == 0) red[w] = s2;
    __syncthreads();
    float tot2 = 0.f;
    for (int ww = 0; ww < nw; ++ww) tot2 += red[ww];
    float var = tot2 / (float)D;
    out[base] = d * rsqrtf(var + 1e-5f) * g[threadIdx.x] + be[threadIdx.x];
}

// ---------------- launcher ----------------
extern "C" void kernel_launch(void* const* d_in, const int* in_sizes, int n_in,
                              void* d_out, int out_size)
{
    const float* x   = (const float*)d_in[0];
    const float* e   = (const float*)d_in[1];
    const float* wq  = (const float*)d_in[2];
    const float* wk  = (const float*)d_in[3];
    const float* wv  = (const float*)d_in[4];
    const float* wem = (const float*)d_in[5];
    const float* wea = (const float*)d_in[6];
    const float* wxo = (const float*)d_in[7];
    const float* weo = (const float*)d_in[8];
    const float* wx1 = (const float*)d_in[9];
    const float* wx2 = (const float*)d_in[10];
    const float* we1 = (const float*)d_in[11];
    const float* we2 = (const float*)d_in[12];
    const float* bq  = (const float*)d_in[13];
    const float* bk  = (const float*)d_in[14];
    const float* bv  = (const float*)d_in[15];
    const float* bem = (const float*)d_in[16];
    const float* bea = (const float*)d_in[17];
    const float* bxo = (const float*)d_in[18];
    const float* beo = (const float*)d_in[19];
    const float* bx1 = (const float*)d_in[20];
    const float* bx2 = (const float*)d_in[21];
    const float* be1 = (const float*)d_in[22];
    const float* be2 = (const float*)d_in[23];
    const float* gnx = (const float*)d_in[24];
    const float* bnx = (const float*)d_in[25];
    const float* gne = (const float*)d_in[26];
    const float* bne = (const float*)d_in[27];

    float* x_out = (float*)d_out;
    float* e_out = (float*)d_out + (size_t)ROWS_X * XD_;

    float *Q, *Km, *newX, *hx, *h1x, *h2x, *wvx, *bvx, *zero, *w2, *beoF;
    char *wemP, *weoP, *w2P, *we1P, *we2P;
    cudaGetSymbolAddress((void**)&Q,    g_Q);
    cudaGetSymbolAddress((void**)&Km,   g_Km);
    cudaGetSymbolAddress((void**)&newX, g_newX);
    cudaGetSymbolAddress((void**)&hx,   g_hx);
    cudaGetSymbolAddress((void**)&h1x,  g_h1x);
    cudaGetSymbolAddress((void**)&h2x,  g_h2x);
    cudaGetSymbolAddress((void**)&wvx,  g_wvx);
    cudaGetSymbolAddress((void**)&bvx,  g_bvx);
    cudaGetSymbolAddress((void**)&zero, g_zero);
    cudaGetSymbolAddress((void**)&w2,   g_w2);
    cudaGetSymbolAddress((void**)&beoF, g_beoF);
    cudaGetSymbolAddress((void**)&wemP, g_wemP);
    cudaGetSymbolAddress((void**)&weoP, g_weoP);
    cudaGetSymbolAddress((void**)&w2P,  g_w2P);
    cudaGetSymbolAddress((void**)&we1P, g_we1P);
    cudaGetSymbolAddress((void**)&we2P, g_we2P);

    cudaFuncSetAttribute(edge_fused_kernel, cudaFuncAttributeMaxDynamicSharedMemorySize, EF_BYTES);
    cudaFuncSetAttribute(prep_all12,        cudaFuncAttributeMaxDynamicSharedMemorySize, 128 * 129 * 4);
    cudaFuncSetAttribute(prep_w2,           cudaFuncAttributeMaxDynamicSharedMemorySize, 128 * 129 * 4);

    // one-time side-stream/event setup (host objects only)
    static cudaStream_t sNode = nullptr, sQK = nullptr, sW2 = nullptr;
    static cudaEvent_t evFork = nullptr, evJoin = nullptr, evQK = nullptr, evW2 = nullptr;
    if (!sNode) {
        cudaStreamCreateWithFlags(&sNode, cudaStreamNonBlocking);
        cudaStreamCreateWithFlags(&sQK,   cudaStreamNonBlocking);
        cudaStreamCreateWithFlags(&sW2,   cudaStreamNonBlocking);
        cudaEventCreateWithFlags(&evFork, cudaEventDisableTiming);
        cudaEventCreateWithFlags(&evJoin, cudaEventDisableTiming);
        cudaEventCreateWithFlags(&evQK,   cudaEventDisableTiming);
        cudaEventCreateWithFlags(&evW2,   cudaEventDisableTiming);
    }

    dim3 blk(256);
    auto grid_of = [](int M, int N) { return dim3((unsigned)(N/64), (unsigned)(M/64)); };

    // ---- fork ----
    cudaEventRecord(evFork, 0);
    cudaStreamWaitEvent(sNode, evFork, 0);
    cudaStreamWaitEvent(sQK,   evFork, 0);
    cudaStreamWaitEvent(sW2,   evFork, 0);

    // node side on sNode (softmax collapses: wV == V; fold wv@wxo)
    gemm_kernel<false><<<grid_of(XD_, XD_), blk, 0, sNode>>>(wv, wxo, zero, wvx, XD_, XD_, XD_, 1.f);
    fold_bias<<<1, 256, 0, sNode>>>(bv, wxo, bxo, bvx);
    gemm_kernel<false><<<grid_of(ROWS_X, XD_), blk, 0, sNode>>>(x, wvx, bvx, newX, ROWS_X, XD_, XD_, 1.f);
    ln_kernel<<<ROWS_X, XD_, 0, sNode>>>(x, newX, gnx, bnx, hx);
    gemm_kernel<true ><<<grid_of(ROWS_X, FFX), blk, 0, sNode>>>(hx,  wx1, bx1, h1x, ROWS_X, FFX, XD_, 1.f);
    gemm_kernel<false><<<grid_of(ROWS_X, XD_), blk, 0, sNode>>>(h1x, wx2, bx2, h2x, ROWS_X, XD_, FFX, 1.f);
    ln_kernel<<<ROWS_X, XD_, 0, sNode>>>(x, h2x, gnx, bnx, x_out);
    cudaEventRecord(evJoin, sNode);

    // Q/K projections on sQK
    gemm_kernel<false><<<grid_of(ROWS_X, XD_), blk, 0, sQK>>>(x, wq, bq, Q,  ROWS_X, XD_, XD_, INV_SQRT_DF);
    gemm_kernel<false><<<grid_of(ROWS_X, XD_), blk, 0, sQK>>>(x, wk, bk, Km, ROWS_X, XD_, XD_, 1.f);
    cudaEventRecord(evQK, sQK);

    // W2 chain on sW2: W2 = wea@weo -> fold_beo -> prep w2 tile
    gemm_kernel<false><<<grid_of(ED_, ED_), blk, 0, sW2>>>(wea, weo, zero, w2, ED_, ED_, XD_, 1.f);
    fold_beo<<<1, 128, 0, sW2>>>(bea, weo, beo, beoF);
    prep_w2<<<1, 256, 128 * 129 * 4, sW2>>>(w2, w2P);
    cudaEventRecord(evW2, sW2);

    // main stream: prep of the 12 direct weight tiles, then edge
    prep_all12<<<12, 256, 128 * 129 * 4>>>(wem, weo, we1, we2, wemP, weoP, we1P, we2P);
    cudaStreamWaitEvent(0, evQK, 0);
    cudaStreamWaitEvent(0, evW2, 0);

    edge_fused_kernel<<<ROWS_E / 64, EDGE_T, EF_BYTES>>>(
        e, Q, Km, w2P, wemP, weoP, we1P, we2P,
        bem, beoF, be1, be2, gne, bne, e_out);

    // ---- join ----
    cudaStreamWaitEvent(0, evJoin, 0);
}

// round 15
// speedup vs baseline: 1.0517x; 1.0517x over previous
#include <cuda_runtime.h>
#include <cuda_bf16.h>
#include <math.h>
#include <stdint.h>

#define BB  8
#define NN  128
#define XD_ 256
#define ED_ 128
#define FFX 1024
#define FFE 512
#define ROWS_X (BB*NN)
#define ROWS_E (BB*NN*NN)
#define INV_SQRT_DF 0.17677669529663687f

#define PITCH   272           // bytes per bf16 tile row (136 bf16)
#define TILE_W  34816         // 128 * 272 (one bf16 128x128 weight tile)

// ---------------- scratch ----------------
__device__ float g_Q   [ROWS_X * XD_];
__device__ float g_Km  [ROWS_X * XD_];
__device__ float g_newX[ROWS_X * XD_];
__device__ float g_hx  [ROWS_X * XD_];
__device__ float g_h1x [ROWS_X * FFX];
__device__ float g_h2x [ROWS_X * XD_];
__device__ float g_wvx [XD_ * XD_];
__device__ float g_bvx [XD_];
__device__ float g_zero[FFX];
__device__ float g_w2  [ED_ * ED_];      // wea @ weo (fp32)
__device__ float g_beoF[ED_];            // beo + bea @ weo
__device__ __align__(16) char g_wemP[2 * TILE_W];
__device__ __align__(16) char g_weoP[2 * TILE_W];
__device__ __align__(16) char g_w2P [TILE_W];
__device__ __align__(16) char g_we1P[4 * TILE_W];
__device__ __align__(16) char g_we2P[4 * TILE_W];

// ---------------- helpers ----------------
__device__ __forceinline__ uint32_t smem_u32(const void* p) {
    uint32_t a;
    asm("{ .reg .u64 t; cvta.to.shared.u64 t, %1; cvt.u32.u64 %0, t; }" : "=r"(a) : "l"(p));
    return a;
}

#define CPA16(dst, src) asm volatile("cp.async.cg.shared.global [%0], [%1], 16;" :: "r"(dst), "l"(src))
#define CP_COMMIT() asm volatile("cp.async.commit_group;" ::: "memory")
#define CP_WAIT0()  asm volatile("cp.async.wait_group 0;" ::: "memory")

__device__ __forceinline__ void prefetch_w(uint32_t dstS, const char* src, int tid) {
    #pragma unroll 4
    for (int t = tid; t < 2176; t += 256)
        CPA16(dstS + (uint32_t)t * 16, src + (size_t)t * 16);
    CP_COMMIT();
}

__device__ __forceinline__ void mma16816(float* c, uint32_t a0, uint32_t a1, uint32_t a2,
                                         uint32_t a3, uint32_t b0, uint32_t b1) {
    asm volatile(
        "mma.sync.aligned.m16n8k16.row.col.f32.bf16.bf16.f32 "
        "{%0,%1,%2,%3},{%4,%5,%6,%7},{%8,%9},{%0,%1,%2,%3};"
        : "+f"(c[0]), "+f"(c[1]), "+f"(c[2]), "+f"(c[3])
        : "r"(a0), "r"(a1), "r"(a2), "r"(a3), "r"(b0), "r"(b1));
}

__device__ __forceinline__ void ldsm4(uint32_t& r0, uint32_t& r1, uint32_t& r2, uint32_t& r3,
                                      uint32_t a) {
    asm volatile("ldmatrix.sync.aligned.m8n8.x4.shared.b16 {%0,%1,%2,%3},[%4];"
                 : "=r"(r0), "=r"(r1), "=r"(r2), "=r"(r3) : "r"(a));
}

// A fragment: 32 rows x 16 k
__device__ __forceinline__ void ldA8(uint32_t a[8], uint32_t base, int r0, int k0, int lane) {
    uint32_t addr = base + (uint32_t)(r0 + (lane & 15)) * PITCH
                  + (uint32_t)(k0 + ((lane >> 4) << 3)) * 2;
    ldsm4(a[0], a[1], a[2], a[3], addr);
    ldsm4(a[4], a[5], a[6], a[7], addr + 16 * PITCH);
}

// B fragment: 32 n x 16 k
__device__ __forceinline__ void ldB8(uint32_t b[8], uint32_t base, int n0, int k0, int lane) {
    uint32_t addr = base + (uint32_t)(n0 + ((lane >> 4) << 3) + (lane & 7)) * PITCH
                  + (uint32_t)(k0 + (((lane >> 3) & 1) << 3)) * 2;
    ldsm4(b[0], b[1], b[2], b[3], addr);
    ldsm4(b[4], b[5], b[6], b[7], addr + 16 * PITCH);
}

__device__ __forceinline__ void mma_pass(float (&acc)[2][4][4], const uint32_t a[8],
                                         const uint32_t b[8]) {
    #pragma unroll
    for (int mf = 0; mf < 2; mf++)
        #pragma unroll
        for (int nf = 0; nf < 4; nf++)
            mma16816(acc[mf][nf], a[mf*4], a[mf*4+1], a[mf*4+2], a[mf*4+3],
                     b[nf*2], b[nf*2+1]);
}

// 1-pass bf16 GEMM tile (M=64 local, K=128) — fully unrolled
__device__ __forceinline__ void compute_ktile(float (&acc)[2][4][4], uint32_t aB,
                                              uint32_t bB, int wm, int wn, int lane) {
    #pragma unroll
    for (int ks = 0; ks < 8; ks++) {
        uint32_t ah[8], bh[8];
        ldA8(ah, aB, wm * 32, ks * 16, lane);
        ldB8(bh, bB, wn * 32, ks * 16, lane);
        mma_pass(acc, ah, bh);
    }
}

__device__ __forceinline__ uint32_t pkf2(float x, float y) {
    __nv_bfloat162 t = __floats2bfloat162_rn(x, y);
    return *reinterpret_cast<uint32_t*>(&t);
}

// stage 64x128 fp32 -> bf16 pitched tile
__device__ __forceinline__ void stage_a_fp32(char* sm, const float* src, int stride, int tid) {
    #pragma unroll 2
    for (int t = tid; t < 2048; t += 256) {
        int r = t >> 5, c4 = (t & 31) << 2;
        float4 v = *(const float4*)(src + (size_t)r * stride + c4);
        uint32_t p0 = pkf2(v.x, v.y);
        uint32_t p1 = pkf2(v.z, v.w);
        *(uint2*)(sm + (uint32_t)r * PITCH + (uint32_t)c4 * 2) = make_uint2(p0, p1);
    }
}

// ---------------- weight prep ----------------
__device__ __forceinline__ void prep_tile(const float* W, char* out, int N, int kc, int nc,
                                          float* tl, int tid) {
    for (int t = tid; t < 16384; t += 256) {
        int k = t >> 7, n = t & 127;
        tl[k * 129 + n] = W[(size_t)(kc * 128 + k) * N + nc * 128 + n];
    }
    __syncthreads();
    for (int t = tid; t < 8192; t += 256) {
        int n = t >> 6, k = (t & 63) << 1;
        float v0 = tl[k * 129 + n], v1 = tl[(k + 1) * 129 + n];
        *(uint32_t*)(out + (uint32_t)n * PITCH + (uint32_t)k * 2) = pkf2(v0, v1);
    }
}

__global__ void prep_all12(const float* __restrict__ wem, const float* __restrict__ weo,
                           const float* __restrict__ we1, const float* __restrict__ we2,
                           char* __restrict__ wemP, char* __restrict__ weoP,
                           char* __restrict__ we1P, char* __restrict__ we2P)
{
    extern __shared__ float tl[];   // 128 x 129
    int s = blockIdx.x;
    const float* W; char* out; int N, kc, nc;
    if (s < 2)       { W = wem; out = wemP + (size_t)s       * TILE_W; N = 256; kc = 0;     nc = s;     }
    else if (s < 4)  { W = weo; out = weoP + (size_t)(s - 2) * TILE_W; N = 128; kc = s - 2; nc = 0;     }
    else if (s < 8)  { W = we1; out = we1P + (size_t)(s - 4) * TILE_W; N = 512; kc = 0;     nc = s - 4; }
    else             { W = we2; out = we2P + (size_t)(s - 8) * TILE_W; N = 128; kc = s - 8; nc = 0;     }
    prep_tile(W, out, N, kc, nc, tl, threadIdx.x);
}

__global__ void prep_w2(const float* __restrict__ w2, char* __restrict__ w2P) {
    extern __shared__ float tl[];
    prep_tile(w2, w2P, 128, 0, 0, tl, threadIdx.x);
}

__global__ void fold_bias(const float* __restrict__ bv, const float* __restrict__ wxo,
                          const float* __restrict__ bxo, float* __restrict__ bvx) {
    int n = threadIdx.x;
    float s = bxo[n];
    for (int k = 0; k < XD_; ++k) s += bv[k] * wxo[k * XD_ + n];
    bvx[n] = s;
}

__global__ void fold_beo(const float* __restrict__ bea, const float* __restrict__ weo,
                         const float* __restrict__ beo, float* __restrict__ beoF) {
    int n = threadIdx.x;
    float s = beo[n];
    for (int c = 0; c < XD_; ++c) s += bea[c] * weo[c * ED_ + n];
    beoF[n] = s;
}

// ================ fused edge kernel, 64-row tiles, 2 CTAs/SM ================
#define R_A   0          // 17408
#define R_B0  17408      // 34816
#define R_B1  52224      // 34816
#define R_C   87040      // 17408
#define R_SM  104448
#define EF_BYTES (104448 + 8192)

__global__ void __launch_bounds__(256, 2) edge_fused_kernel(
    const float* __restrict__ e, const float* __restrict__ Qs, const float* __restrict__ Km,
    const char* __restrict__ w2P, const char* __restrict__ wemP, const char* __restrict__ weoP,
    const char* __restrict__ we1P, const char* __restrict__ we2P,
    const float* __restrict__ bem, const float* __restrict__ beoF,
    const float* __restrict__ be1, const float* __restrict__ be2,
    const float* __restrict__ gne, const float* __restrict__ bne,
    float* __restrict__ e_out)
{
    extern __shared__ char sm[];
    const int tid = threadIdx.x;
    const int lane = tid & 31, w = tid >> 5;
    const int wm = w & 1, wn = w >> 1;      // 2 x 4 warp grid
    const int g = lane >> 2, q = lane & 3;
    const int blk = blockIdx.x;
    const size_t row0 = (size_t)blk * 64;
    const int b = (int)(row0 >> 14);
    const int i = (int)((row0 >> 7) & 127);
    const int j0 = (int)(row0 & 127);       // 0 or 64

    uint32_t smB = smem_u32(sm);
    float* qS   = (float*)(sm + R_SM);              // 256
    float* bemS = qS + 256;                          // 256
    float* beoS = bemS + 256;                        // 128
    float* gneS = beoS + 128;                        // 128
    float* bneS = gneS + 128;                        // 128
    float* be1S = bneS + 128;                        // 512
    float* be2S = be1S + 512;                        // 128
    float* red  = be2S + 128;                        // 256
    float* red2 = red + 256;                         // 256

    const uint32_t aB = smB + R_A;
    const uint32_t cB = smB + R_C;
    const uint32_t Bb[2] = {smB + R_B0, smB + R_B1};
    const char* tiles[13] = {
        w2P, wemP, weoP, wemP + TILE_W, weoP + TILE_W,
        we1P,              we2P,
        we1P + TILE_W,     we2P + TILE_W,
        we1P + 2 * TILE_W, we2P + 2 * TILE_W,
        we1P + 3 * TILE_W, we2P + 3 * TILE_W};

    prefetch_w(Bb[0], tiles[0], tid);               // tile 0 in flight
    stage_a_fp32(sm + R_A, e + row0 * ED_, ED_, tid);
    qS[tid]   = Qs[((size_t)(b * NN + i)) * XD_ + tid];
    bemS[tid] = bem[tid];
    if (tid < 128) { beoS[tid] = beoF[tid]; gneS[tid] = gne[tid]; bneS[tid] = bne[tid]; }
    if (tid < 128) be2S[tid] = be2[tid];
    for (int t = tid; t < 512; t += 256) be1S[t] = be1[t];
    CP_WAIT0(); __syncthreads();
    prefetch_w(Bb[1], tiles[1], tid);               // tile 1 in flight

    // =================== attention phase ===================
    float accNE[2][4][4] = {};

    // ---- phase 0: accNE = e @ W2   (collapsed E2 path)
    compute_ktile(accNE, aB, Bb[0], wm, wn, lane);
    CP_WAIT0(); __syncthreads();
    prefetch_w(Bb[0], tiles[2], tid);

    #pragma unroll 1
    for (int nc = 0; nc < 2; nc++) {
        const int p = 1 + nc * 2;
        // ---- phase p (wem[nc]): E1 = e@wem; Y = q*km*(E1+bem+1) -> bf16 into C
        {
            float acc[2][4][4] = {};
            compute_ktile(acc, aB, Bb[p & 1], wm, wn, lane);
            #pragma unroll
            for (int mf = 0; mf < 2; mf++)
            #pragma unroll
            for (int h = 0; h < 2; h++) {
                int r = wm * 32 + mf * 16 + h * 8 + g;
                const float* kp = Km + ((size_t)(b * NN + j0 + r)) * XD_ + nc * 128;
                #pragma unroll
                for (int nf = 0; nf < 4; nf++) {
                    int cl = wn * 32 + nf * 8 + q * 2;
                    int cg = nc * 128 + cl;
                    float2 km = *(const float2*)(kp + cl);
                    float y0 = qS[cg]   * km.x * (acc[mf][nf][h*2]   + bemS[cg]   + 1.f);
                    float y1 = qS[cg+1] * km.y * (acc[mf][nf][h*2+1] + bemS[cg+1] + 1.f);
                    *(uint32_t*)(sm + R_C + (uint32_t)r * PITCH + (uint32_t)cl * 2) = pkf2(y0, y1);
                }
            }
        }
        CP_WAIT0(); __syncthreads();
        prefetch_w(Bb[p & 1], tiles[p + 2], tid);
        // ---- phase p+1 (weo[nc]): accNE += Y @ weo
        compute_ktile(accNE, cB, Bb[(p + 1) & 1], wm, wn, lane);
        CP_WAIT0(); __syncthreads();
        prefetch_w(Bb[(p + 1) & 1], tiles[p + 3], tid);
    }

    // ---- attn epilogue: he = LN(e + accNE + beoF)*gne + bne -> bf16 INTO A REGION
    #pragma unroll
    for (int mf = 0; mf < 2; mf++)
    #pragma unroll
    for (int h = 0; h < 2; h++) {
        int r = wm * 32 + mf * 16 + h * 8 + g;
        #pragma unroll
        for (int nf = 0; nf < 4; nf++) {
            int cl = wn * 32 + nf * 8 + q * 2;
            float2 ev = *(const float2*)(e + (row0 + r) * ED_ + cl);
            accNE[mf][nf][h*2+0] += beoS[cl]   + ev.x;
            accNE[mf][nf][h*2+1] += beoS[cl+1] + ev.y;
        }
    }
    {
        float mean[2][2], rstd[2][2];
        #pragma unroll
        for (int mf = 0; mf < 2; mf++)
        #pragma unroll
        for (int h = 0; h < 2; h++) {
            float s = 0.f;
            #pragma unroll
            for (int nf = 0; nf < 4; nf++) s += accNE[mf][nf][h*2] + accNE[mf][nf][h*2+1];
            s += __shfl_xor_sync(0xffffffffu, s, 1);
            s += __shfl_xor_sync(0xffffffffu, s, 2);
            if (q == 0) red[wn * 64 + wm * 32 + mf * 16 + h * 8 + g] = s;
        }
        __syncthreads();
        #pragma unroll
        for (int mf = 0; mf < 2; mf++)
        #pragma unroll
        for (int h = 0; h < 2; h++) {
            int r = wm * 32 + mf * 16 + h * 8 + g;
            mean[mf][h] = (red[r] + red[64 + r] + red[128 + r] + red[192 + r]) * (1.f / 128.f);
            float s = 0.f;
            #pragma unroll
            for (int nf = 0; nf < 4; nf++) {
                float d0 = accNE[mf][nf][h*2]   - mean[mf][h];
                float d1 = accNE[mf][nf][h*2+1] - mean[mf][h];
                s += d0 * d0 + d1 * d1;
            }
            s += __shfl_xor_sync(0xffffffffu, s, 1);
            s += __shfl_xor_sync(0xffffffffu, s, 2);
            if (q == 0) red2[wn * 64 + r] = s;
        }
        __syncthreads();
        #pragma unroll
        for (int mf = 0; mf < 2; mf++)
        #pragma unroll
        for (int h = 0; h < 2; h++) {
            int r = wm * 32 + mf * 16 + h * 8 + g;
            rstd[mf][h] = rsqrtf((red2[r] + red2[64 + r] + red2[128 + r] + red2[192 + r])
                                 * (1.f / 128.f) + 1e-5f);
            #pragma unroll
            for (int nf = 0; nf < 4; nf++) {
                int cl = wn * 32 + nf * 8 + q * 2;
                float o0 = (accNE[mf][nf][h*2]   - mean[mf][h]) * rstd[mf][h] * gneS[cl]   + bneS[cl];
                float o1 = (accNE[mf][nf][h*2+1] - mean[mf][h]) * rstd[mf][h] * gneS[cl+1] + bneS[cl+1];
                // he -> A region, MMA layout (e-tile is dead now)
                *(uint32_t*)(sm + R_A + (uint32_t)r * PITCH + (uint32_t)cl * 2) = pkf2(o0, o1);
            }
        }
    }
    __syncthreads();   // he visible to all warps before FF ktiles

    // =================== FF phase (A = he, C = h1 chunks) ===================
    float accH2[2][4][4] = {};

    #pragma unroll 1
    for (int p = 0; p < 4; p++) {
        const int i0 = 5 + p * 2;
        // ---- tile i0 (we1[p]): h1 = relu(he@we1 + be1) -> bf16 into C
        {
            float acc[2][4][4] = {};
            compute_ktile(acc, aB, Bb[i0 & 1], wm, wn, lane);
            #pragma unroll
            for (int mf = 0; mf < 2; mf++)
            #pragma unroll
            for (int h = 0; h < 2; h++) {
                int r = wm * 32 + mf * 16 + h * 8 + g;
                #pragma unroll
                for (int nf = 0; nf < 4; nf++) {
                    int cl = wn * 32 + nf * 8 + q * 2;
                    int cgl = p * 128 + cl;
                    float o0 = fmaxf(acc[mf][nf][h*2]   + be1S[cgl],   0.f);
                    float o1 = fmaxf(acc[mf][nf][h*2+1] + be1S[cgl+1], 0.f);
                    *(uint32_t*)(sm + R_C + (uint32_t)r * PITCH + (uint32_t)cl * 2) = pkf2(o0, o1);
                }
            }
        }
        CP_WAIT0(); __syncthreads();
        if (i0 + 2 < 13) prefetch_w(Bb[i0 & 1], tiles[i0 + 2], tid);
        // ---- tile i0+1 (we2[p]): h2 += h1chunk @ we2
        compute_ktile(accH2, cB, Bb[(i0 + 1) & 1], wm, wn, lane);
        CP_WAIT0(); __syncthreads();
        if (i0 + 3 < 13) prefetch_w(Bb[(i0 + 1) & 1], tiles[i0 + 3], tid);
    }

    // ---- FF epilogue: e_out = LN(e + h2 + be2) * gne + bne
    #pragma unroll
    for (int mf = 0; mf < 2; mf++)
    #pragma unroll
    for (int h = 0; h < 2; h++) {
        int r = wm * 32 + mf * 16 + h * 8 + g;
        #pragma unroll
        for (int nf = 0; nf < 4; nf++) {
            int cl = wn * 32 + nf * 8 + q * 2;
            float2 ev = *(const float2*)(e + (row0 + r) * ED_ + cl);
            accH2[mf][nf][h*2+0] += be2S[cl]   + ev.x;
            accH2[mf][nf][h*2+1] += be2S[cl+1] + ev.y;
        }
    }
    float mean[2][2], rstd[2][2];
    #pragma unroll
    for (int mf = 0; mf < 2; mf++)
    #pragma unroll
    for (int h = 0; h < 2; h++) {
        float s = 0.f;
        #pragma unroll
        for (int nf = 0; nf < 4; nf++) s += accH2[mf][nf][h*2] + accH2[mf][nf][h*2+1];
        s += __shfl_xor_sync(0xffffffffu, s, 1);
        s += __shfl_xor_sync(0xffffffffu, s, 2);
        if (q == 0) red[wn * 64 + wm * 32 + mf * 16 + h * 8 + g] = s;
    }
    __syncthreads();
    #pragma unroll
    for (int mf = 0; mf < 2; mf++)
    #pragma unroll
    for (int h = 0; h < 2; h++) {
        int r = wm * 32 + mf * 16 + h * 8 + g;
        mean[mf][h] = (red[r] + red[64 + r] + red[128 + r] + red[192 + r]) * (1.f / 128.f);
        float s = 0.f;
        #pragma unroll
        for (int nf = 0; nf < 4; nf++) {
            float d0 = accH2[mf][nf][h*2]   - mean[mf][h];
            float d1 = accH2[mf][nf][h*2+1] - mean[mf][h];
            s += d0 * d0 + d1 * d1;
        }
        s += __shfl_xor_sync(0xffffffffu, s, 1);
        s += __shfl_xor_sync(0xffffffffu, s, 2);
        if (q == 0) red2[wn * 64 + r] = s;
    }
    __syncthreads();
    #pragma unroll
    for (int mf = 0; mf < 2; mf++)
    #pragma unroll
    for (int h = 0; h < 2; h++) {
        int r = wm * 32 + mf * 16 + h * 8 + g;
        rstd[mf][h] = rsqrtf((red2[r] + red2[64 + r] + red2[128 + r] + red2[192 + r])
                             * (1.f / 128.f) + 1e-5f);
        #pragma unroll
        for (int nf = 0; nf < 4; nf++) {
            int cl = wn * 32 + nf * 8 + q * 2;
            float o0 = (accH2[mf][nf][h*2]   - mean[mf][h]) * rstd[mf][h] * gneS[cl]   + bneS[cl];
            float o1 = (accH2[mf][nf][h*2+1] - mean[mf][h]) * rstd[mf][h] * gneS[cl+1] + bneS[cl+1];
            *(float2*)(e_out + (row0 + r) * ED_ + cl) = make_float2(o0, o1);
        }
    }
}

// ---------------- node-side SIMT GEMM + LN ----------------
template<bool RELU>
__global__ void __launch_bounds__(256) gemm_kernel(
    const float* __restrict__ A, const float* __restrict__ W,
    const float* __restrict__ bias, float* __restrict__ C,
    int M, int N, int K, float alpha)
{
    __shared__ __align__(16) float aS[64][68];
    __shared__ __align__(16) float wS[64][68];
    const int tid = threadIdx.x;
    const int tx  = tid & 15;
    const int ty  = tid >> 4;
    const size_t row0 = (size_t)blockIdx.y * 64;
    const int    col0 = blockIdx.x * 64;
    float acc[4][4] = {};
    for (int k0 = 0; k0 < K; k0 += 64) {
        #pragma unroll
        for (int t = tid; t < 1024; t += 256) {
            int r = t >> 4, c4 = (t & 15) << 2;
            float4 av = *(const float4*)(A + (row0 + r) * K + k0 + c4);
            aS[r][c4+0]=av.x; aS[r][c4+1]=av.y; aS[r][c4+2]=av.z; aS[r][c4+3]=av.w;
            float4 wv = *(const float4*)(W + (size_t)(k0 + r) * N + col0 + c4);
            wS[r][c4+0]=wv.x; wS[r][c4+1]=wv.y; wS[r][c4+2]=wv.z; wS[r][c4+3]=wv.w;
        }
        __syncthreads();
        #pragma unroll 16
        for (int k = 0; k < 64; ++k) {
            float a0=aS[ty*4+0][k], a1=aS[ty*4+1][k], a2=aS[ty*4+2][k], a3=aS[ty*4+3][k];
            float4 bv = *(const float4*)&wS[k][tx*4];
            acc[0][0]+=a0*bv.x; acc[0][1]+=a0*bv.y; acc[0][2]+=a0*bv.z; acc[0][3]+=a0*bv.w;
            acc[1][0]+=a1*bv.x; acc[1][1]+=a1*bv.y; acc[1][2]+=a1*bv.z; acc[1][3]+=a1*bv.w;
            acc[2][0]+=a2*bv.x; acc[2][1]+=a2*bv.y; acc[2][2]+=a2*bv.z; acc[2][3]+=a2*bv.w;
            acc[3][0]+=a3*bv.x; acc[3][1]+=a3*bv.y; acc[3][2]+=a3*bv.z; acc[3][3]+=a3*bv.w;
        }
        __syncthreads();
    }
    const int c = col0 + tx * 4;
    float b0=bias[c+0], b1=bias[c+1], b2=bias[c+2], b3=bias[c+3];
    #pragma unroll
    for (int m = 0; m < 4; ++m) {
        float4 o;
        o.x = alpha*(acc[m][0]+b0); o.y = alpha*(acc[m][1]+b1);
        o.z = alpha*(acc[m][2]+b2); o.w = alpha*(acc[m][3]+b3);
        if (RELU) { o.x=fmaxf(o.x,0.f); o.y=fmaxf(o.y,0.f); o.z=fmaxf(o.z,0.f); o.w=fmaxf(o.w,0.f); }
        *(float4*)(C + (row0 + ty*4 + m) * N + c) = o;
    }
}

__global__ void ln_kernel(const float* __restrict__ A, const float* __restrict__ Bv,
                          const float* __restrict__ g, const float* __restrict__ be,
                          float* __restrict__ out)
{
    __shared__ float red[8];
    const int D = blockDim.x;
    const size_t base = (size_t)blockIdx.x * D + threadIdx.x;
    const int lane = threadIdx.x & 31;
    const int w    = threadIdx.x >> 5;
    const int nw   = D >> 5;
    float v = A[base] + Bv[base];
    float s = v;
    #pragma unroll
    for (int o = 16; o; o >>= 1) s += __shfl_xor_sync(0xffffffffu, s, o);
    if (lane == 0) red[w] = s;
    __syncthreads();
    float tot = 0.f;
    for (int ww = 0; ww < nw; ++ww) tot += red[ww];
    float mean = tot / (float)D;
    float d = v - mean;
    __syncthreads();
    float s2 = d * d;
    #pragma unroll
    for (int o = 16; o; o >>= 1) s2 += __shfl_xor_sync(0xffffffffu, s2, o);
    if (lane == 0) red[w] = s2;
    __syncthreads();
    float tot2 = 0.f;
    for (int ww = 0; ww < nw; ++ww) tot2 += red[ww];
    float var = tot2 / (float)D;
    out[base] = d * rsqrtf(var + 1e-5f) * g[threadIdx.x] + be[threadIdx.x];
}

// ---------------- launcher ----------------
extern "C" void kernel_launch(void* const* d_in, const int* in_sizes, int n_in,
                              void* d_out, int out_size)
{
    const float* x   = (const float*)d_in[0];
    const float* e   = (const float*)d_in[1];
    const float* wq  = (const float*)d_in[2];
    const float* wk  = (const float*)d_in[3];
    const float* wv  = (const float*)d_in[4];
    const float* wem = (const float*)d_in[5];
    const float* wea = (const float*)d_in[6];
    const float* wxo = (const float*)d_in[7];
    const float* weo = (const float*)d_in[8];
    const float* wx1 = (const float*)d_in[9];
    const float* wx2 = (const float*)d_in[10];
    const float* we1 = (const float*)d_in[11];
    const float* we2 = (const float*)d_in[12];
    const float* bq  = (const float*)d_in[13];
    const float* bk  = (const float*)d_in[14];
    const float* bv  = (const float*)d_in[15];
    const float* bem = (const float*)d_in[16];
    const float* bea = (const float*)d_in[17];
    const float* bxo = (const float*)d_in[18];
    const float* beo = (const float*)d_in[19];
    const float* bx1 = (const float*)d_in[20];
    const float* bx2 = (const float*)d_in[21];
    const float* be1 = (const float*)d_in[22];
    const float* be2 = (const float*)d_in[23];
    const float* gnx = (const float*)d_in[24];
    const float* bnx = (const float*)d_in[25];
    const float* gne = (const float*)d_in[26];
    const float* bne = (const float*)d_in[27];

    float* x_out = (float*)d_out;
    float* e_out = (float*)d_out + (size_t)ROWS_X * XD_;

    float *Q, *Km, *newX, *hx, *h1x, *h2x, *wvx, *bvx, *zero, *w2, *beoF;
    char *wemP, *weoP, *w2P, *we1P, *we2P;
    cudaGetSymbolAddress((void**)&Q,    g_Q);
    cudaGetSymbolAddress((void**)&Km,   g_Km);
    cudaGetSymbolAddress((void**)&newX, g_newX);
    cudaGetSymbolAddress((void**)&hx,   g_hx);
    cudaGetSymbolAddress((void**)&h1x,  g_h1x);
    cudaGetSymbolAddress((void**)&h2x,  g_h2x);
    cudaGetSymbolAddress((void**)&wvx,  g_wvx);
    cudaGetSymbolAddress((void**)&bvx,  g_bvx);
    cudaGetSymbolAddress((void**)&zero, g_zero);
    cudaGetSymbolAddress((void**)&w2,   g_w2);
    cudaGetSymbolAddress((void**)&beoF, g_beoF);
    cudaGetSymbolAddress((void**)&wemP, g_wemP);
    cudaGetSymbolAddress((void**)&weoP, g_weoP);
    cudaGetSymbolAddress((void**)&w2P,  g_w2P);
    cudaGetSymbolAddress((void**)&we1P, g_we1P);
    cudaGetSymbolAddress((void**)&we2P, g_we2P);

    cudaFuncSetAttribute(edge_fused_kernel, cudaFuncAttributeMaxDynamicSharedMemorySize, EF_BYTES);
    cudaFuncSetAttribute(prep_all12,        cudaFuncAttributeMaxDynamicSharedMemorySize, 128 * 129 * 4);
    cudaFuncSetAttribute(prep_w2,           cudaFuncAttributeMaxDynamicSharedMemorySize, 128 * 129 * 4);

    // one-time side-stream/event setup (host objects only)
    static cudaStream_t sNode = nullptr, sQK = nullptr, sW2 = nullptr;
    static cudaEvent_t evFork = nullptr, evJoin = nullptr, evQK = nullptr, evW2 = nullptr;
    if (!sNode) {
        cudaStreamCreateWithFlags(&sNode, cudaStreamNonBlocking);
        cudaStreamCreateWithFlags(&sQK,   cudaStreamNonBlocking);
        cudaStreamCreateWithFlags(&sW2,   cudaStreamNonBlocking);
        cudaEventCreateWithFlags(&evFork, cudaEventDisableTiming);
        cudaEventCreateWithFlags(&evJoin, cudaEventDisableTiming);
        cudaEventCreateWithFlags(&evQK,   cudaEventDisableTiming);
        cudaEventCreateWithFlags(&evW2,   cudaEventDisableTiming);
    }

    dim3 blk(256);
    auto grid_of = [](int M, int N) { return dim3((unsigned)(N/64), (unsigned)(M/64)); };

    // ---- fork ----
    cudaEventRecord(evFork, 0);
    cudaStreamWaitEvent(sNode, evFork, 0);
    cudaStreamWaitEvent(sQK,   evFork, 0);
    cudaStreamWaitEvent(sW2,   evFork, 0);

    // node side on sNode (softmax collapses: wV == V; fold wv@wxo)
    gemm_kernel<false><<<grid_of(XD_, XD_), blk, 0, sNode>>>(wv, wxo, zero, wvx, XD_, XD_, XD_, 1.f);
    fold_bias<<<1, 256, 0, sNode>>>(bv, wxo, bxo, bvx);
    gemm_kernel<false><<<grid_of(ROWS_X, XD_), blk, 0, sNode>>>(x, wvx, bvx, newX, ROWS_X, XD_, XD_, 1.f);
    ln_kernel<<<ROWS_X, XD_, 0, sNode>>>(x, newX, gnx, bnx, hx);
    gemm_kernel<true ><<<grid_of(ROWS_X, FFX), blk, 0, sNode>>>(hx,  wx1, bx1, h1x, ROWS_X, FFX, XD_, 1.f);
    gemm_kernel<false><<<grid_of(ROWS_X, XD_), blk, 0, sNode>>>(h1x, wx2, bx2, h2x, ROWS_X, XD_, FFX, 1.f);
    ln_kernel<<<ROWS_X, XD_, 0, sNode>>>(x, h2x, gnx, bnx, x_out);
    cudaEventRecord(evJoin, sNode);

    // Q/K projections on sQK
    gemm_kernel<false><<<grid_of(ROWS_X, XD_), blk, 0, sQK>>>(x, wq, bq, Q,  ROWS_X, XD_, XD_, INV_SQRT_DF);
    gemm_kernel<false><<<grid_of(ROWS_X, XD_), blk, 0, sQK>>>(x, wk, bk, Km, ROWS_X, XD_, XD_, 1.f);
    cudaEventRecord(evQK, sQK);

    // W2 chain on sW2: W2 = wea@weo -> fold_beo -> prep w2 tile
    gemm_kernel<false><<<grid_of(ED_, ED_), blk, 0, sW2>>>(wea, weo, zero, w2, ED_, ED_, XD_, 1.f);
    fold_beo<<<1, 128, 0, sW2>>>(bea, weo, beo, beoF);
    prep_w2<<<1, 256, 128 * 129 * 4, sW2>>>(w2, w2P);
    cudaEventRecord(evW2, sW2);

    // main stream: prep of the 12 direct weight tiles, then edge
    prep_all12<<<12, 256, 128 * 129 * 4>>>(wem, weo, we1, we2, wemP, weoP, we1P, we2P);
    cudaStreamWaitEvent(0, evQK, 0);
    cudaStreamWaitEvent(0, evW2, 0);

    edge_fused_kernel<<<ROWS_E / 64, blk, EF_BYTES>>>(
        e, Q, Km, w2P, wemP, weoP, we1P, we2P,
        bem, beoF, be1, be2, gne, bne, e_out);

    // ---- join ----
    cudaStreamWaitEvent(0, evJoin, 0);
}

// round 16
// speedup vs baseline: 1.0651x; 1.0127x over previous
#include <cuda_runtime.h>
#include <cuda_bf16.h>
#include <math.h>
#include <stdint.h>

#define BB  8
#define NN  128
#define XD_ 256
#define ED_ 128
#define FFX 1024
#define FFE 512
#define ROWS_X (BB*NN)
#define ROWS_E (BB*NN*NN)
#define INV_SQRT_DF 0.17677669529663687f

#define PITCH   272           // bytes per bf16 tile row (136 bf16)
#define TILE_W  34816         // 128 * 272 (one bf16 128x128 weight tile)

// ---------------- scratch ----------------
__device__ float g_Q   [ROWS_X * XD_];
__device__ float g_Km  [ROWS_X * XD_];
__device__ float g_newX[ROWS_X * XD_];
__device__ float g_hx  [ROWS_X * XD_];
__device__ float g_h1x [ROWS_X * FFX];
__device__ float g_h2x [ROWS_X * XD_];
__device__ float g_wvx [XD_ * XD_];
__device__ float g_bvx [XD_];
__device__ float g_zero[FFX];
__device__ float g_w2  [ED_ * ED_];      // wea @ weo (fp32)
__device__ float g_beoF[ED_];            // beo + bea @ weo
__device__ __align__(16) char g_wemP[2 * TILE_W];
__device__ __align__(16) char g_weoP[2 * TILE_W];
__device__ __align__(16) char g_w2P [TILE_W];
__device__ __align__(16) char g_we1P[4 * TILE_W];
__device__ __align__(16) char g_we2P[4 * TILE_W];

// ---------------- helpers ----------------
__device__ __forceinline__ uint32_t smem_u32(const void* p) {
    uint32_t a;
    asm("{ .reg .u64 t; cvta.to.shared.u64 t, %1; cvt.u32.u64 %0, t; }" : "=r"(a) : "l"(p));
    return a;
}

#define CPA16(dst, src) asm volatile("cp.async.cg.shared.global [%0], [%1], 16;" :: "r"(dst), "l"(src))
#define CP_COMMIT() asm volatile("cp.async.commit_group;" ::: "memory")
#define CP_WAIT0()  asm volatile("cp.async.wait_group 0;" ::: "memory")

__device__ __forceinline__ void prefetch_w(uint32_t dstS, const char* src, int tid) {
    #pragma unroll 4
    for (int t = tid; t < 2176; t += 256)
        CPA16(dstS + (uint32_t)t * 16, src + (size_t)t * 16);
    CP_COMMIT();
}

__device__ __forceinline__ void mma16816(float* c, uint32_t a0, uint32_t a1, uint32_t a2,
                                         uint32_t a3, uint32_t b0, uint32_t b1) {
    asm volatile(
        "mma.sync.aligned.m16n8k16.row.col.f32.bf16.bf16.f32 "
        "{%0,%1,%2,%3},{%4,%5,%6,%7},{%8,%9},{%0,%1,%2,%3};"
        : "+f"(c[0]), "+f"(c[1]), "+f"(c[2]), "+f"(c[3])
        : "r"(a0), "r"(a1), "r"(a2), "r"(a3), "r"(b0), "r"(b1));
}

__device__ __forceinline__ void ldsm4(uint32_t& r0, uint32_t& r1, uint32_t& r2, uint32_t& r3,
                                      uint32_t a) {
    asm volatile("ldmatrix.sync.aligned.m8n8.x4.shared.b16 {%0,%1,%2,%3},[%4];"
                 : "=r"(r0), "=r"(r1), "=r"(r2), "=r"(r3) : "r"(a));
}

// A fragment: 32 rows x 16 k
__device__ __forceinline__ void ldA8(uint32_t a[8], uint32_t base, int r0, int k0, int lane) {
    uint32_t addr = base + (uint32_t)(r0 + (lane & 15)) * PITCH
                  + (uint32_t)(k0 + ((lane >> 4) << 3)) * 2;
    ldsm4(a[0], a[1], a[2], a[3], addr);
    ldsm4(a[4], a[5], a[6], a[7], addr + 16 * PITCH);
}

// B fragment: 32 n x 16 k
__device__ __forceinline__ void ldB8(uint32_t b[8], uint32_t base, int n0, int k0, int lane) {
    uint32_t addr = base + (uint32_t)(n0 + ((lane >> 4) << 3) + (lane & 7)) * PITCH
                  + (uint32_t)(k0 + (((lane >> 3) & 1) << 3)) * 2;
    ldsm4(b[0], b[1], b[2], b[3], addr);
    ldsm4(b[4], b[5], b[6], b[7], addr + 16 * PITCH);
}

__device__ __forceinline__ void mma_pass(float (&acc)[2][4][4], const uint32_t a[8],
                                         const uint32_t b[8]) {
    #pragma unroll
    for (int mf = 0; mf < 2; mf++)
        #pragma unroll
        for (int nf = 0; nf < 4; nf++)
            mma16816(acc[mf][nf], a[mf*4], a[mf*4+1], a[mf*4+2], a[mf*4+3],
                     b[nf*2], b[nf*2+1]);
}

// 1-pass bf16 GEMM tile (M=64 local, K=128)
__device__ __forceinline__ void compute_ktile(float (&acc)[2][4][4], uint32_t aB,
                                              uint32_t bB, int wm, int wn, int lane) {
    #pragma unroll 2
    for (int ks = 0; ks < 8; ks++) {
        uint32_t ah[8], bh[8];
        ldA8(ah, aB, wm * 32, ks * 16, lane);
        ldB8(bh, bB, wn * 32, ks * 16, lane);
        mma_pass(acc, ah, bh);
    }
}

__device__ __forceinline__ uint32_t pkf2(float x, float y) {
    __nv_bfloat162 t = __floats2bfloat162_rn(x, y);
    return *reinterpret_cast<uint32_t*>(&t);
}

// stage 64x128 fp32 -> bf16 pitched tile
__device__ __forceinline__ void stage_a_fp32(char* sm, const float* src, int stride, int tid) {
    #pragma unroll 2
    for (int t = tid; t < 2048; t += 256) {
        int r = t >> 5, c4 = (t & 31) << 2;
        float4 v = *(const float4*)(src + (size_t)r * stride + c4);
        uint32_t p0 = pkf2(v.x, v.y);
        uint32_t p1 = pkf2(v.z, v.w);
        *(uint2*)(sm + (uint32_t)r * PITCH + (uint32_t)c4 * 2) = make_uint2(p0, p1);
    }
}

// ---------------- weight prep ----------------
__device__ __forceinline__ void prep_tile(const float* W, char* out, int N, int kc, int nc,
                                          float* tl, int tid) {
    for (int t = tid; t < 16384; t += 256) {
        int k = t >> 7, n = t & 127;
        tl[k * 129 + n] = W[(size_t)(kc * 128 + k) * N + nc * 128 + n];
    }
    __syncthreads();
    for (int t = tid; t < 8192; t += 256) {
        int n = t >> 6, k = (t & 63) << 1;
        float v0 = tl[k * 129 + n], v1 = tl[(k + 1) * 129 + n];
        *(uint32_t*)(out + (uint32_t)n * PITCH + (uint32_t)k * 2) = pkf2(v0, v1);
    }
}

__global__ void prep_all12(const float* __restrict__ wem, const float* __restrict__ weo,
                           const float* __restrict__ we1, const float* __restrict__ we2,
                           char* __restrict__ wemP, char* __restrict__ weoP,
                           char* __restrict__ we1P, char* __restrict__ we2P)
{
    extern __shared__ float tl[];   // 128 x 129
    int s = blockIdx.x;
    const float* W; char* out; int N, kc, nc;
    if (s < 2)       { W = wem; out = wemP + (size_t)s       * TILE_W; N = 256; kc = 0;     nc = s;     }
    else if (s < 4)  { W = weo; out = weoP + (size_t)(s - 2) * TILE_W; N = 128; kc = s - 2; nc = 0;     }
    else if (s < 8)  { W = we1; out = we1P + (size_t)(s - 4) * TILE_W; N = 512; kc = 0;     nc = s - 4; }
    else             { W = we2; out = we2P + (size_t)(s - 8) * TILE_W; N = 128; kc = s - 8; nc = 0;     }
    prep_tile(W, out, N, kc, nc, tl, threadIdx.x);
}

__global__ void prep_w2(const float* __restrict__ w2, char* __restrict__ w2P) {
    extern __shared__ float tl[];
    prep_tile(w2, w2P, 128, 0, 0, tl, threadIdx.x);
}

__global__ void fold_bias(const float* __restrict__ bv, const float* __restrict__ wxo,
                          const float* __restrict__ bxo, float* __restrict__ bvx) {
    int n = threadIdx.x;
    float s = bxo[n];
    for (int k = 0; k < XD_; ++k) s += bv[k] * wxo[k * XD_ + n];
    bvx[n] = s;
}

__global__ void fold_beo(const float* __restrict__ bea, const float* __restrict__ weo,
                         const float* __restrict__ beo, float* __restrict__ beoF) {
    int n = threadIdx.x;
    float s = beo[n];
    for (int c = 0; c < XD_; ++c) s += bea[c] * weo[c * ED_ + n];
    beoF[n] = s;
}

// ================ fused edge kernel, 64-row tiles, 2 CTAs/SM ================
#define R_A   0          // 17408
#define R_B0  17408      // 34816
#define R_B1  52224      // 34816
#define R_C   87040      // 17408
#define R_SM  104448
#define EF_BYTES (104448 + 8192)

__global__ void __launch_bounds__(256, 2) edge_fused_kernel(
    const float* __restrict__ e, const float* __restrict__ Qs, const float* __restrict__ Km,
    const char* __restrict__ w2P, const char* __restrict__ wemP, const char* __restrict__ weoP,
    const char* __restrict__ we1P, const char* __restrict__ we2P,
    const float* __restrict__ bem, const float* __restrict__ beoF,
    const float* __restrict__ be1, const float* __restrict__ be2,
    const float* __restrict__ gne, const float* __restrict__ bne,
    float* __restrict__ e_out)
{
    extern __shared__ char sm[];
    const int tid = threadIdx.x;
    const int lane = tid & 31, w = tid >> 5;
    const int wm = w & 1, wn = w >> 1;      // 2 x 4 warp grid
    const int g = lane >> 2, q = lane & 3;
    const int blk = blockIdx.x;
    const size_t row0 = (size_t)blk * 64;
    const int b = (int)(row0 >> 14);
    const int i = (int)((row0 >> 7) & 127);
    const int j0 = (int)(row0 & 127);       // 0 or 64

    uint32_t smB = smem_u32(sm);
    float* qS   = (float*)(sm + R_SM);              // 256
    float* bemS = qS + 256;                          // 256
    float* beoS = bemS + 256;                        // 128
    float* gneS = beoS + 128;                        // 128
    float* bneS = gneS + 128;                        // 128
    float* be1S = bneS + 128;                        // 512
    float* be2S = be1S + 512;                        // 128
    float* red  = be2S + 128;                        // 256 (sum)
    float* red2 = red + 256;                         // 256 (sumsq)

    const uint32_t aB = smB + R_A;
    const uint32_t cB = smB + R_C;
    const uint32_t Bb[2] = {smB + R_B0, smB + R_B1};
    const char* tiles[13] = {
        w2P, wemP, weoP, wemP + TILE_W, weoP + TILE_W,
        we1P,              we2P,
        we1P + TILE_W,     we2P + TILE_W,
        we1P + 2 * TILE_W, we2P + 2 * TILE_W,
        we1P + 3 * TILE_W, we2P + 3 * TILE_W};

    prefetch_w(Bb[0], tiles[0], tid);               // tile 0 in flight
    stage_a_fp32(sm + R_A, e + row0 * ED_, ED_, tid);
    qS[tid]   = Qs[((size_t)(b * NN + i)) * XD_ + tid];
    bemS[tid] = bem[tid];
    if (tid < 128) { beoS[tid] = beoF[tid]; gneS[tid] = gne[tid]; bneS[tid] = bne[tid]; }
    if (tid < 128) be2S[tid] = be2[tid];
    for (int t = tid; t < 512; t += 256) be1S[t] = be1[t];
    CP_WAIT0(); __syncthreads();
    prefetch_w(Bb[1], tiles[1], tid);               // tile 1 in flight

    // =================== attention phase ===================
    float accNE[2][4][4] = {};

    // ---- phase 0: accNE = e @ W2   (collapsed E2 path)
    compute_ktile(accNE, aB, Bb[0], wm, wn, lane);
    CP_WAIT0(); __syncthreads();
    prefetch_w(Bb[0], tiles[2], tid);

    #pragma unroll 1
    for (int nc = 0; nc < 2; nc++) {
        const int p = 1 + nc * 2;
        // ---- phase p (wem[nc]): E1 = e@wem; Y = q*km*(E1+bem+1) -> bf16 into C
        {
            float acc[2][4][4] = {};
            compute_ktile(acc, aB, Bb[p & 1], wm, wn, lane);
            #pragma unroll
            for (int mf = 0; mf < 2; mf++)
            #pragma unroll
            for (int h = 0; h < 2; h++) {
                int r = wm * 32 + mf * 16 + h * 8 + g;
                const float* kp = Km + ((size_t)(b * NN + j0 + r)) * XD_ + nc * 128;
                #pragma unroll
                for (int nf = 0; nf < 4; nf++) {
                    int cl = wn * 32 + nf * 8 + q * 2;
                    int cg = nc * 128 + cl;
                    float2 km = *(const float2*)(kp + cl);
                    float y0 = qS[cg]   * km.x * (acc[mf][nf][h*2]   + bemS[cg]   + 1.f);
                    float y1 = qS[cg+1] * km.y * (acc[mf][nf][h*2+1] + bemS[cg+1] + 1.f);
                    *(uint32_t*)(sm + R_C + (uint32_t)r * PITCH + (uint32_t)cl * 2) = pkf2(y0, y1);
                }
            }
        }
        CP_WAIT0(); __syncthreads();
        prefetch_w(Bb[p & 1], tiles[p + 2], tid);
        // ---- phase p+1 (weo[nc]): accNE += Y @ weo
        compute_ktile(accNE, cB, Bb[(p + 1) & 1], wm, wn, lane);
        CP_WAIT0(); __syncthreads();
        prefetch_w(Bb[(p + 1) & 1], tiles[p + 3], tid);
    }

    // ---- attn epilogue: he = LN(e + accNE + beoF)*gne + bne -> bf16 INTO A REGION
    #pragma unroll
    for (int mf = 0; mf < 2; mf++)
    #pragma unroll
    for (int h = 0; h < 2; h++) {
        int r = wm * 32 + mf * 16 + h * 8 + g;
        #pragma unroll
        for (int nf = 0; nf < 4; nf++) {
            int cl = wn * 32 + nf * 8 + q * 2;
            float2 ev = *(const float2*)(e + (row0 + r) * ED_ + cl);
            accNE[mf][nf][h*2+0] += beoS[cl]   + ev.x;
            accNE[mf][nf][h*2+1] += beoS[cl+1] + ev.y;
        }
    }
    {
        // single-pass LN: fused sum + sumsq reduction, one barrier
        #pragma unroll
        for (int mf = 0; mf < 2; mf++)
        #pragma unroll
        for (int h = 0; h < 2; h++) {
            float s = 0.f, s2 = 0.f;
            #pragma unroll
            for (int nf = 0; nf < 4; nf++) {
                float v0 = accNE[mf][nf][h*2], v1 = accNE[mf][nf][h*2+1];
                s += v0 + v1;
                s2 += v0 * v0 + v1 * v1;
            }
            s  += __shfl_xor_sync(0xffffffffu, s, 1);
            s2 += __shfl_xor_sync(0xffffffffu, s2, 1);
            s  += __shfl_xor_sync(0xffffffffu, s, 2);
            s2 += __shfl_xor_sync(0xffffffffu, s2, 2);
            if (q == 0) {
                red[wn * 64 + wm * 32 + mf * 16 + h * 8 + g]  = s;
                red2[wn * 64 + wm * 32 + mf * 16 + h * 8 + g] = s2;
            }
        }
        __syncthreads();
        #pragma unroll
        for (int mf = 0; mf < 2; mf++)
        #pragma unroll
        for (int h = 0; h < 2; h++) {
            int r = wm * 32 + mf * 16 + h * 8 + g;
            float mean = (red[r] + red[64 + r] + red[128 + r] + red[192 + r]) * (1.f / 128.f);
            float ex2  = (red2[r] + red2[64 + r] + red2[128 + r] + red2[192 + r]) * (1.f / 128.f);
            float rstd = rsqrtf(fmaxf(ex2 - mean * mean, 0.f) + 1e-5f);
            #pragma unroll
            for (int nf = 0; nf < 4; nf++) {
                int cl = wn * 32 + nf * 8 + q * 2;
                float o0 = (accNE[mf][nf][h*2]   - mean) * rstd * gneS[cl]   + bneS[cl];
                float o1 = (accNE[mf][nf][h*2+1] - mean) * rstd * gneS[cl+1] + bneS[cl+1];
                // he -> A region, MMA layout (e-tile is dead now)
                *(uint32_t*)(sm + R_A + (uint32_t)r * PITCH + (uint32_t)cl * 2) = pkf2(o0, o1);
            }
        }
    }
    __syncthreads();   // he visible to all warps before FF ktiles

    // =================== FF phase (A = he, C = h1 chunks) ===================
    float accH2[2][4][4] = {};

    #pragma unroll 1
    for (int p = 0; p < 4; p++) {
        const int i0 = 5 + p * 2;
        // ---- tile i0 (we1[p]): h1 = relu(he@we1 + be1) -> bf16 into C
        {
            float acc[2][4][4] = {};
            compute_ktile(acc, aB, Bb[i0 & 1], wm, wn, lane);
            #pragma unroll
            for (int mf = 0; mf < 2; mf++)
            #pragma unroll
            for (int h = 0; h < 2; h++) {
                int r = wm * 32 + mf * 16 + h * 8 + g;
                #pragma unroll
                for (int nf = 0; nf < 4; nf++) {
                    int cl = wn * 32 + nf * 8 + q * 2;
                    int cgl = p * 128 + cl;
                    float o0 = fmaxf(acc[mf][nf][h*2]   + be1S[cgl],   0.f);
                    float o1 = fmaxf(acc[mf][nf][h*2+1] + be1S[cgl+1], 0.f);
                    *(uint32_t*)(sm + R_C + (uint32_t)r * PITCH + (uint32_t)cl * 2) = pkf2(o0, o1);
                }
            }
        }
        CP_WAIT0(); __syncthreads();
        if (i0 + 2 < 13) prefetch_w(Bb[i0 & 1], tiles[i0 + 2], tid);
        // ---- tile i0+1 (we2[p]): h2 += h1chunk @ we2
        compute_ktile(accH2, cB, Bb[(i0 + 1) & 1], wm, wn, lane);
        CP_WAIT0(); __syncthreads();
        if (i0 + 3 < 13) prefetch_w(Bb[(i0 + 1) & 1], tiles[i0 + 3], tid);
    }

    // ---- FF epilogue: e_out = LN(e + h2 + be2) * gne + bne (single-pass LN)
    #pragma unroll
    for (int mf = 0; mf < 2; mf++)
    #pragma unroll
    for (int h = 0; h < 2; h++) {
        int r = wm * 32 + mf * 16 + h * 8 + g;
        #pragma unroll
        for (int nf = 0; nf < 4; nf++) {
            int cl = wn * 32 + nf * 8 + q * 2;
            float2 ev = *(const float2*)(e + (row0 + r) * ED_ + cl);
            accH2[mf][nf][h*2+0] += be2S[cl]   + ev.x;
            accH2[mf][nf][h*2+1] += be2S[cl+1] + ev.y;
        }
    }
    #pragma unroll
    for (int mf = 0; mf < 2; mf++)
    #pragma unroll
    for (int h = 0; h < 2; h++) {
        float s = 0.f, s2 = 0.f;
        #pragma unroll
        for (int nf = 0; nf < 4; nf++) {
            float v0 = accH2[mf][nf][h*2], v1 = accH2[mf][nf][h*2+1];
            s += v0 + v1;
            s2 += v0 * v0 + v1 * v1;
        }
        s  += __shfl_xor_sync(0xffffffffu, s, 1);
        s2 += __shfl_xor_sync(0xffffffffu, s2, 1);
        s  += __shfl_xor_sync(0xffffffffu, s, 2);
        s2 += __shfl_xor_sync(0xffffffffu, s2, 2);
        if (q == 0) {
            red[wn * 64 + wm * 32 + mf * 16 + h * 8 + g]  = s;
            red2[wn * 64 + wm * 32 + mf * 16 + h * 8 + g] = s2;
        }
    }
    __syncthreads();
    #pragma unroll
    for (int mf = 0; mf < 2; mf++)
    #pragma unroll
    for (int h = 0; h < 2; h++) {
        int r = wm * 32 + mf * 16 + h * 8 + g;
        float mean = (red[r] + red[64 + r] + red[128 + r] + red[192 + r]) * (1.f / 128.f);
        float ex2  = (red2[r] + red2[64 + r] + red2[128 + r] + red2[192 + r]) * (1.f / 128.f);
        float rstd = rsqrtf(fmaxf(ex2 - mean * mean, 0.f) + 1e-5f);
        #pragma unroll
        for (int nf = 0; nf < 4; nf++) {
            int cl = wn * 32 + nf * 8 + q * 2;
            float o0 = (accH2[mf][nf][h*2]   - mean) * rstd * gneS[cl]   + bneS[cl];
            float o1 = (accH2[mf][nf][h*2+1] - mean) * rstd * gneS[cl+1] + bneS[cl+1];
            *(float2*)(e_out + (row0 + r) * ED_ + cl) = make_float2(o0, o1);
        }
    }
}

// ---------------- node-side SIMT GEMM + LN ----------------
template<bool RELU>
__global__ void __launch_bounds__(256) gemm_kernel(
    const float* __restrict__ A, const float* __restrict__ W,
    const float* __restrict__ bias, float* __restrict__ C,
    int M, int N, int K, float alpha)
{
    __shared__ __align__(16) float aS[64][68];
    __shared__ __align__(16) float wS[64][68];
    const int tid = threadIdx.x;
    const int tx  = tid & 15;
    const int ty  = tid >> 4;
    const size_t row0 = (size_t)blockIdx.y * 64;
    const int    col0 = blockIdx.x * 64;
    float acc[4][4] = {};
    for (int k0 = 0; k0 < K; k0 += 64) {
        #pragma unroll
        for (int t = tid; t < 1024; t += 256) {
            int r = t >> 4, c4 = (t & 15) << 2;
            float4 av = *(const float4*)(A + (row0 + r) * K + k0 + c4);
            aS[r][c4+0]=av.x; aS[r][c4+1]=av.y; aS[r][c4+2]=av.z; aS[r][c4+3]=av.w;
            float4 wv = *(const float4*)(W + (size_t)(k0 + r) * N + col0 + c4);
            wS[r][c4+0]=wv.x; wS[r][c4+1]=wv.y; wS[r][c4+2]=wv.z; wS[r][c4+3]=wv.w;
        }
        __syncthreads();
        #pragma unroll 16
        for (int k = 0; k < 64; ++k) {
            float a0=aS[ty*4+0][k], a1=aS[ty*4+1][k], a2=aS[ty*4+2][k], a3=aS[ty*4+3][k];
            float4 bv = *(const float4*)&wS[k][tx*4];
            acc[0][0]+=a0*bv.x; acc[0][1]+=a0*bv.y; acc[0][2]+=a0*bv.z; acc[0][3]+=a0*bv.w;
            acc[1][0]+=a1*bv.x; acc[1][1]+=a1*bv.y; acc[1][2]+=a1*bv.z; acc[1][3]+=a1*bv.w;
            acc[2][0]+=a2*bv.x; acc[2][1]+=a2*bv.y; acc[2][2]+=a2*bv.z; acc[2][3]+=a2*bv.w;
            acc[3][0]+=a3*bv.x; acc[3][1]+=a3*bv.y; acc[3][2]+=a3*bv.z; acc[3][3]+=a3*bv.w;
        }
        __syncthreads();
    }
    const int c = col0 + tx * 4;
    float b0=bias[c+0], b1=bias[c+1], b2=bias[c+2], b3=bias[c+3];
    #pragma unroll
    for (int m = 0; m < 4; ++m) {
        float4 o;
        o.x = alpha*(acc[m][0]+b0); o.y = alpha*(acc[m][1]+b1);
        o.z = alpha*(acc[m][2]+b2); o.w = alpha*(acc[m][3]+b3);
        if (RELU) { o.x=fmaxf(o.x,0.f); o.y=fmaxf(o.y,0.f); o.z=fmaxf(o.z,0.f); o.w=fmaxf(o.w,0.f); }
        *(float4*)(C + (row0 + ty*4 + m) * N + c) = o;
    }
}

__global__ void ln_kernel(const float* __restrict__ A, const float* __restrict__ Bv,
                          const float* __restrict__ g, const float* __restrict__ be,
                          float* __restrict__ out)
{
    __shared__ float red[8];
    const int D = blockDim.x;
    const size_t base = (size_t)blockIdx.x * D + threadIdx.x;
    const int lane = threadIdx.x & 31;
    const int w    = threadIdx.x >> 5;
    const int nw   = D >> 5;
    float v = A[base] + Bv[base];
    float s = v;
    #pragma unroll
    for (int o = 16; o; o >>= 1) s += __shfl_xor_sync(0xffffffffu, s, o);
    if (lane == 0) red[w] = s;
    __syncthreads();
    float tot = 0.f;
    for (int ww = 0; ww < nw; ++ww) tot += red[ww];
    float mean = tot / (float)D;
    float d = v - mean;
    __syncthreads();
    float s2 = d * d;
    #pragma unroll
    for (int o = 16; o; o >>= 1) s2 += __shfl_xor_sync(0xffffffffu, s2, o);
    if (lane == 0) red[w] = s2;
    __syncthreads();
    float tot2 = 0.f;
    for (int ww = 0; ww < nw; ++ww) tot2 += red[ww];
    float var = tot2 / (float)D;
    out[base] = d * rsqrtf(var + 1e-5f) * g[threadIdx.x] + be[threadIdx.x];
}

// ---------------- launcher ----------------
extern "C" void kernel_launch(void* const* d_in, const int* in_sizes, int n_in,
                              void* d_out, int out_size)
{
    const float* x   = (const float*)d_in[0];
    const float* e   = (const float*)d_in[1];
    const float* wq  = (const float*)d_in[2];
    const float* wk  = (const float*)d_in[3];
    const float* wv  = (const float*)d_in[4];
    const float* wem = (const float*)d_in[5];
    const float* wea = (const float*)d_in[6];
    const float* wxo = (const float*)d_in[7];
    const float* weo = (const float*)d_in[8];
    const float* wx1 = (const float*)d_in[9];
    const float* wx2 = (const float*)d_in[10];
    const float* we1 = (const float*)d_in[11];
    const float* we2 = (const float*)d_in[12];
    const float* bq  = (const float*)d_in[13];
    const float* bk  = (const float*)d_in[14];
    const float* bv  = (const float*)d_in[15];
    const float* bem = (const float*)d_in[16];
    const float* bea = (const float*)d_in[17];
    const float* bxo = (const float*)d_in[18];
    const float* beo = (const float*)d_in[19];
    const float* bx1 = (const float*)d_in[20];
    const float* bx2 = (const float*)d_in[21];
    const float* be1 = (const float*)d_in[22];
    const float* be2 = (const float*)d_in[23];
    const float* gnx = (const float*)d_in[24];
    const float* bnx = (const float*)d_in[25];
    const float* gne = (const float*)d_in[26];
    const float* bne = (const float*)d_in[27];

    float* x_out = (float*)d_out;
    float* e_out = (float*)d_out + (size_t)ROWS_X * XD_;

    float *Q, *Km, *newX, *hx, *h1x, *h2x, *wvx, *bvx, *zero, *w2, *beoF;
    char *wemP, *weoP, *w2P, *we1P, *we2P;
    cudaGetSymbolAddress((void**)&Q,    g_Q);
    cudaGetSymbolAddress((void**)&Km,   g_Km);
    cudaGetSymbolAddress((void**)&newX, g_newX);
    cudaGetSymbolAddress((void**)&hx,   g_hx);
    cudaGetSymbolAddress((void**)&h1x,  g_h1x);
    cudaGetSymbolAddress((void**)&h2x,  g_h2x);
    cudaGetSymbolAddress((void**)&wvx,  g_wvx);
    cudaGetSymbolAddress((void**)&bvx,  g_bvx);
    cudaGetSymbolAddress((void**)&zero, g_zero);
    cudaGetSymbolAddress((void**)&w2,   g_w2);
    cudaGetSymbolAddress((void**)&beoF, g_beoF);
    cudaGetSymbolAddress((void**)&wemP, g_wemP);
    cudaGetSymbolAddress((void**)&weoP, g_weoP);
    cudaGetSymbolAddress((void**)&w2P,  g_w2P);
    cudaGetSymbolAddress((void**)&we1P, g_we1P);
    cudaGetSymbolAddress((void**)&we2P, g_we2P);

    cudaFuncSetAttribute(edge_fused_kernel, cudaFuncAttributeMaxDynamicSharedMemorySize, EF_BYTES);
    cudaFuncSetAttribute(prep_all12,        cudaFuncAttributeMaxDynamicSharedMemorySize, 128 * 129 * 4);
    cudaFuncSetAttribute(prep_w2,           cudaFuncAttributeMaxDynamicSharedMemorySize, 128 * 129 * 4);

    // one-time side-stream/event setup (host objects only)
    static cudaStream_t sNode = nullptr, sQK = nullptr, sW2 = nullptr;
    static cudaEvent_t evFork = nullptr, evJoin = nullptr, evQK = nullptr, evW2 = nullptr;
    if (!sNode) {
        cudaStreamCreateWithFlags(&sNode, cudaStreamNonBlocking);
        cudaStreamCreateWithFlags(&sQK,   cudaStreamNonBlocking);
        cudaStreamCreateWithFlags(&sW2,   cudaStreamNonBlocking);
        cudaEventCreateWithFlags(&evFork, cudaEventDisableTiming);
        cudaEventCreateWithFlags(&evJoin, cudaEventDisableTiming);
        cudaEventCreateWithFlags(&evQK,   cudaEventDisableTiming);
        cudaEventCreateWithFlags(&evW2,   cudaEventDisableTiming);
    }

    dim3 blk(256);
    auto grid_of = [](int M, int N) { return dim3((unsigned)(N/64), (unsigned)(M/64)); };

    // ---- fork ----
    cudaEventRecord(evFork, 0);
    cudaStreamWaitEvent(sNode, evFork, 0);
    cudaStreamWaitEvent(sQK,   evFork, 0);
    cudaStreamWaitEvent(sW2,   evFork, 0);

    // node side on sNode (softmax collapses: wV == V; fold wv@wxo)
    gemm_kernel<false><<<grid_of(XD_, XD_), blk, 0, sNode>>>(wv, wxo, zero, wvx, XD_, XD_, XD_, 1.f);
    fold_bias<<<1, 256, 0, sNode>>>(bv, wxo, bxo, bvx);
    gemm_kernel<false><<<grid_of(ROWS_X, XD_), blk, 0, sNode>>>(x, wvx, bvx, newX, ROWS_X, XD_, XD_, 1.f);
    ln_kernel<<<ROWS_X, XD_, 0, sNode>>>(x, newX, gnx, bnx, hx);
    gemm_kernel<true ><<<grid_of(ROWS_X, FFX), blk, 0, sNode>>>(hx,  wx1, bx1, h1x, ROWS_X, FFX, XD_, 1.f);
    gemm_kernel<false><<<grid_of(ROWS_X, XD_), blk, 0, sNode>>>(h1x, wx2, bx2, h2x, ROWS_X, XD_, FFX, 1.f);
    ln_kernel<<<ROWS_X, XD_, 0, sNode>>>(x, h2x, gnx, bnx, x_out);
    cudaEventRecord(evJoin, sNode);

    // Q/K projections on sQK
    gemm_kernel<false><<<grid_of(ROWS_X, XD_), blk, 0, sQK>>>(x, wq, bq, Q,  ROWS_X, XD_, XD_, INV_SQRT_DF);
    gemm_kernel<false><<<grid_of(ROWS_X, XD_), blk, 0, sQK>>>(x, wk, bk, Km, ROWS_X, XD_, XD_, 1.f);
    cudaEventRecord(evQK, sQK);

    // W2 chain on sW2: W2 = wea@weo -> fold_beo -> prep w2 tile
    gemm_kernel<false><<<grid_of(ED_, ED_), blk, 0, sW2>>>(wea, weo, zero, w2, ED_, ED_, XD_, 1.f);
    fold_beo<<<1, 128, 0, sW2>>>(bea, weo, beo, beoF);
    prep_w2<<<1, 256, 128 * 129 * 4, sW2>>>(w2, w2P);
    cudaEventRecord(evW2, sW2);

    // main stream: prep of the 12 direct weight tiles, then edge
    prep_all12<<<12, 256, 128 * 129 * 4>>>(wem, weo, we1, we2, wemP, weoP, we1P, we2P);
    cudaStreamWaitEvent(0, evQK, 0);
    cudaStreamWaitEvent(0, evW2, 0);

    edge_fused_kernel<<<ROWS_E / 64, blk, EF_BYTES>>>(
        e, Q, Km, w2P, wemP, weoP, we1P, we2P,
        bem, beoF, be1, be2, gne, bne, e_out);

    // ---- join ----
    cudaStreamWaitEvent(0, evJoin, 0);
}

// round 17
// speedup vs baseline: 1.0756x; 1.0099x over previous
#include <cuda_runtime.h>
#include <cuda_bf16.h>
#include <math.h>
#include <stdint.h>

#define BB  8
#define NN  128
#define XD_ 256
#define ED_ 128
#define FFX 1024
#define FFE 512
#define ROWS_X (BB*NN)
#define ROWS_E (BB*NN*NN)
#define INV_SQRT_DF 0.17677669529663687f

#define PITCH   272           // bytes per bf16 tile row (136 bf16)
#define TILE_W  34816         // 128 * 272 (one bf16 128x128 weight tile)

// ---------------- scratch ----------------
__device__ float g_Q   [ROWS_X * XD_];
__device__ float g_Km  [ROWS_X * XD_];
__device__ float g_newX[ROWS_X * XD_];
__device__ float g_hx  [ROWS_X * XD_];
__device__ float g_h1x [ROWS_X * FFX];
__device__ float g_h2x [ROWS_X * XD_];
__device__ float g_wvx [XD_ * XD_];
__device__ float g_bvx [XD_];
__device__ float g_zero[FFX];
__device__ float g_w2  [ED_ * ED_];      // wea @ weo (fp32)
__device__ float g_beoF[ED_];            // beo + bea @ weo
__device__ __align__(16) char g_wemP[2 * TILE_W];
__device__ __align__(16) char g_weoP[2 * TILE_W];
__device__ __align__(16) char g_w2P [TILE_W];
__device__ __align__(16) char g_we1P[4 * TILE_W];
__device__ __align__(16) char g_we2P[4 * TILE_W];

// ---------------- helpers ----------------
__device__ __forceinline__ uint32_t smem_u32(const void* p) {
    uint32_t a;
    asm("{ .reg .u64 t; cvta.to.shared.u64 t, %1; cvt.u32.u64 %0, t; }" : "=r"(a) : "l"(p));
    return a;
}

#define CPA16(dst, src) asm volatile("cp.async.cg.shared.global [%0], [%1], 16;" :: "r"(dst), "l"(src))
#define CP_COMMIT() asm volatile("cp.async.commit_group;" ::: "memory")
#define CP_WAIT0()  asm volatile("cp.async.wait_group 0;" ::: "memory")

__device__ __forceinline__ void prefetch_w(uint32_t dstS, const char* src, int tid) {
    #pragma unroll 4
    for (int t = tid; t < 2176; t += 256)
        CPA16(dstS + (uint32_t)t * 16, src + (size_t)t * 16);
    CP_COMMIT();
}

__device__ __forceinline__ void mma16816(float* c, uint32_t a0, uint32_t a1, uint32_t a2,
                                         uint32_t a3, uint32_t b0, uint32_t b1) {
    asm volatile(
        "mma.sync.aligned.m16n8k16.row.col.f32.bf16.bf16.f32 "
        "{%0,%1,%2,%3},{%4,%5,%6,%7},{%8,%9},{%0,%1,%2,%3};"
        : "+f"(c[0]), "+f"(c[1]), "+f"(c[2]), "+f"(c[3])
        : "r"(a0), "r"(a1), "r"(a2), "r"(a3), "r"(b0), "r"(b1));
}

__device__ __forceinline__ void ldsm4(uint32_t& r0, uint32_t& r1, uint32_t& r2, uint32_t& r3,
                                      uint32_t a) {
    asm volatile("ldmatrix.sync.aligned.m8n8.x4.shared.b16 {%0,%1,%2,%3},[%4];"
                 : "=r"(r0), "=r"(r1), "=r"(r2), "=r"(r3) : "r"(a));
}

// A fragment: 32 rows x 16 k
__device__ __forceinline__ void ldA8(uint32_t a[8], uint32_t base, int r0, int k0, int lane) {
    uint32_t addr = base + (uint32_t)(r0 + (lane & 15)) * PITCH
                  + (uint32_t)(k0 + ((lane >> 4) << 3)) * 2;
    ldsm4(a[0], a[1], a[2], a[3], addr);
    ldsm4(a[4], a[5], a[6], a[7], addr + 16 * PITCH);
}

// B fragment: 32 n x 16 k
__device__ __forceinline__ void ldB8(uint32_t b[8], uint32_t base, int n0, int k0, int lane) {
    uint32_t addr = base + (uint32_t)(n0 + ((lane >> 4) << 3) + (lane & 7)) * PITCH
                  + (uint32_t)(k0 + (((lane >> 3) & 1) << 3)) * 2;
    ldsm4(b[0], b[1], b[2], b[3], addr);
    ldsm4(b[4], b[5], b[6], b[7], addr + 16 * PITCH);
}

__device__ __forceinline__ void mma_pass(float (&acc)[2][4][4], const uint32_t a[8],
                                         const uint32_t b[8]) {
    #pragma unroll
    for (int mf = 0; mf < 2; mf++)
        #pragma unroll
        for (int nf = 0; nf < 4; nf++)
            mma16816(acc[mf][nf], a[mf*4], a[mf*4+1], a[mf*4+2], a[mf*4+3],
                     b[nf*2], b[nf*2+1]);
}

// 1-pass bf16 GEMM tile (M=64 local, K=128)
__device__ __forceinline__ void compute_ktile(float (&acc)[2][4][4], uint32_t aB,
                                              uint32_t bB, int wm, int wn, int lane) {
    #pragma unroll 2
    for (int ks = 0; ks < 8; ks++) {
        uint32_t ah[8], bh[8];
        ldA8(ah, aB, wm * 32, ks * 16, lane);
        ldB8(bh, bB, wn * 32, ks * 16, lane);
        mma_pass(acc, ah, bh);
    }
}

__device__ __forceinline__ uint32_t pkf2(float x, float y) {
    __nv_bfloat162 t = __floats2bfloat162_rn(x, y);
    return *reinterpret_cast<uint32_t*>(&t);
}

// stage 64x128 fp32 -> bf16 pitched tile
__device__ __forceinline__ void stage_a_fp32(char* sm, const float* src, int stride, int tid) {
    #pragma unroll 2
    for (int t = tid; t < 2048; t += 256) {
        int r = t >> 5, c4 = (t & 31) << 2;
        float4 v = *(const float4*)(src + (size_t)r * stride + c4);
        uint32_t p0 = pkf2(v.x, v.y);
        uint32_t p1 = pkf2(v.z, v.w);
        *(uint2*)(sm + (uint32_t)r * PITCH + (uint32_t)c4 * 2) = make_uint2(p0, p1);
    }
}

// ---------------- weight prep ----------------
__device__ __forceinline__ void prep_tile(const float* W, char* out, int N, int kc, int nc,
                                          float* tl, int tid) {
    for (int t = tid; t < 16384; t += 256) {
        int k = t >> 7, n = t & 127;
        tl[k * 129 + n] = W[(size_t)(kc * 128 + k) * N + nc * 128 + n];
    }
    __syncthreads();
    for (int t = tid; t < 8192; t += 256) {
        int n = t >> 6, k = (t & 63) << 1;
        float v0 = tl[k * 129 + n], v1 = tl[(k + 1) * 129 + n];
        *(uint32_t*)(out + (uint32_t)n * PITCH + (uint32_t)k * 2) = pkf2(v0, v1);
    }
}

__global__ void prep_all12(const float* __restrict__ wem, const float* __restrict__ weo,
                           const float* __restrict__ we1, const float* __restrict__ we2,
                           char* __restrict__ wemP, char* __restrict__ weoP,
                           char* __restrict__ we1P, char* __restrict__ we2P)
{
    extern __shared__ float tl[];   // 128 x 129
    int s = blockIdx.x;
    const float* W; char* out; int N, kc, nc;
    if (s < 2)       { W = wem; out = wemP + (size_t)s       * TILE_W; N = 256; kc = 0;     nc = s;     }
    else if (s < 4)  { W = weo; out = weoP + (size_t)(s - 2) * TILE_W; N = 128; kc = s - 2; nc = 0;     }
    else if (s < 8)  { W = we1; out = we1P + (size_t)(s - 4) * TILE_W; N = 512; kc = 0;     nc = s - 4; }
    else             { W = we2; out = we2P + (size_t)(s - 8) * TILE_W; N = 128; kc = s - 8; nc = 0;     }
    prep_tile(W, out, N, kc, nc, tl, threadIdx.x);
}

__global__ void prep_w2(const float* __restrict__ w2, char* __restrict__ w2P) {
    extern __shared__ float tl[];
    prep_tile(w2, w2P, 128, 0, 0, tl, threadIdx.x);
}

__global__ void fold_bias(const float* __restrict__ bv, const float* __restrict__ wxo,
                          const float* __restrict__ bxo, float* __restrict__ bvx) {
    int n = threadIdx.x;
    float s = bxo[n];
    for (int k = 0; k < XD_; ++k) s += bv[k] * wxo[k * XD_ + n];
    bvx[n] = s;
}

__global__ void fold_beo(const float* __restrict__ bea, const float* __restrict__ weo,
                         const float* __restrict__ beo, float* __restrict__ beoF) {
    int n = threadIdx.x;
    float s = beo[n];
    for (int c = 0; c < XD_; ++c) s += bea[c] * weo[c * ED_ + n];
    beoF[n] = s;
}

// ================ fused edge kernel, 64-row tiles, 2 CTAs/SM ================
#define R_A   0          // 17408
#define R_B0  17408      // 34816
#define R_B1  52224      // 34816
#define R_C   87040      // 17408
#define R_SM  104448
#define EF_BYTES (104448 + 8192)

__global__ void __launch_bounds__(256, 2) edge_fused_kernel(
    const float* __restrict__ e, const float* __restrict__ Qs, const float* __restrict__ Km,
    const char* __restrict__ w2P, const char* __restrict__ wemP, const char* __restrict__ weoP,
    const char* __restrict__ we1P, const char* __restrict__ we2P,
    const float* __restrict__ bem, const float* __restrict__ beoF,
    const float* __restrict__ be1, const float* __restrict__ be2,
    const float* __restrict__ gne, const float* __restrict__ bne,
    float* __restrict__ e_out)
{
    extern __shared__ char sm[];
    const int tid = threadIdx.x;
    const int lane = tid & 31, w = tid >> 5;
    const int wm = w & 1, wn = w >> 1;      // 2 x 4 warp grid
    const int g = lane >> 2, q = lane & 3;
    const int blk = blockIdx.x;
    const size_t row0 = (size_t)blk * 64;
    const int b = (int)(row0 >> 14);
    const int i = (int)((row0 >> 7) & 127);
    const int j0 = (int)(row0 & 127);       // 0 or 64

    uint32_t smB = smem_u32(sm);
    float* qS   = (float*)(sm + R_SM);              // 256
    float* bemS = qS + 256;                          // 256
    float* beoS = bemS + 256;                        // 128
    float* gneS = beoS + 128;                        // 128
    float* bneS = gneS + 128;                        // 128
    float* be1S = bneS + 128;                        // 512
    float* be2S = be1S + 512;                        // 128
    float* red  = be2S + 128;                        // 256 (sum)
    float* red2 = red + 256;                         // 256 (sumsq)

    const uint32_t aB = smB + R_A;
    const uint32_t cB = smB + R_C;
    const uint32_t Bb[2] = {smB + R_B0, smB + R_B1};
    const char* tiles[13] = {
        w2P, wemP, weoP, wemP + TILE_W, weoP + TILE_W,
        we1P,              we2P,
        we1P + TILE_W,     we2P + TILE_W,
        we1P + 2 * TILE_W, we2P + 2 * TILE_W,
        we1P + 3 * TILE_W, we2P + 3 * TILE_W};

    prefetch_w(Bb[0], tiles[0], tid);               // tile 0 in flight
    stage_a_fp32(sm + R_A, e + row0 * ED_, ED_, tid);
    qS[tid]   = Qs[((size_t)(b * NN + i)) * XD_ + tid];
    bemS[tid] = bem[tid];
    if (tid < 128) { beoS[tid] = beoF[tid]; gneS[tid] = gne[tid]; bneS[tid] = bne[tid]; }
    if (tid < 128) be2S[tid] = be2[tid];
    for (int t = tid; t < 512; t += 256) be1S[t] = be1[t];
    CP_WAIT0(); __syncthreads();
    prefetch_w(Bb[1], tiles[1], tid);               // tile 1 in flight

    // =================== attention phase ===================
    float accNE[2][4][4] = {};

    // ---- phase 0: accNE = e @ W2   (collapsed E2 path)
    compute_ktile(accNE, aB, Bb[0], wm, wn, lane);
    CP_WAIT0(); __syncthreads();
    prefetch_w(Bb[0], tiles[2], tid);

    #pragma unroll 1
    for (int nc = 0; nc < 2; nc++) {
        const int p = 1 + nc * 2;
        // ---- phase p (wem[nc]): E1 = e@wem; Y = q*km*(E1+bem+1) -> bf16 into C
        {
            float acc[2][4][4] = {};
            compute_ktile(acc, aB, Bb[p & 1], wm, wn, lane);
            #pragma unroll
            for (int mf = 0; mf < 2; mf++)
            #pragma unroll
            for (int h = 0; h < 2; h++) {
                int r = wm * 32 + mf * 16 + h * 8 + g;
                const float* kp = Km + ((size_t)(b * NN + j0 + r)) * XD_ + nc * 128;
                #pragma unroll
                for (int nf = 0; nf < 4; nf++) {
                    int cl = wn * 32 + nf * 8 + q * 2;
                    int cg = nc * 128 + cl;
                    float2 km = *(const float2*)(kp + cl);
                    float y0 = qS[cg]   * km.x * (acc[mf][nf][h*2]   + bemS[cg]   + 1.f);
                    float y1 = qS[cg+1] * km.y * (acc[mf][nf][h*2+1] + bemS[cg+1] + 1.f);
                    *(uint32_t*)(sm + R_C + (uint32_t)r * PITCH + (uint32_t)cl * 2) = pkf2(y0, y1);
                }
            }
        }
        CP_WAIT0(); __syncthreads();
        prefetch_w(Bb[p & 1], tiles[p + 2], tid);
        // ---- phase p+1 (weo[nc]): accNE += Y @ weo
        compute_ktile(accNE, cB, Bb[(p + 1) & 1], wm, wn, lane);
        CP_WAIT0(); __syncthreads();
        prefetch_w(Bb[(p + 1) & 1], tiles[p + 3], tid);
    }

    // ---- attn epilogue: he = LN(e + accNE + beoF)*gne + bne -> bf16 INTO A REGION
    #pragma unroll
    for (int mf = 0; mf < 2; mf++)
    #pragma unroll
    for (int h = 0; h < 2; h++) {
        int r = wm * 32 + mf * 16 + h * 8 + g;
        #pragma unroll
        for (int nf = 0; nf < 4; nf++) {
            int cl = wn * 32 + nf * 8 + q * 2;
            float2 ev = *(const float2*)(e + (row0 + r) * ED_ + cl);
            accNE[mf][nf][h*2+0] += beoS[cl]   + ev.x;
            accNE[mf][nf][h*2+1] += beoS[cl+1] + ev.y;
        }
    }
    {
        // single-pass LN: fused sum + sumsq reduction, one barrier
        #pragma unroll
        for (int mf = 0; mf < 2; mf++)
        #pragma unroll
        for (int h = 0; h < 2; h++) {
            float s = 0.f, s2 = 0.f;
            #pragma unroll
            for (int nf = 0; nf < 4; nf++) {
                float v0 = accNE[mf][nf][h*2], v1 = accNE[mf][nf][h*2+1];
                s += v0 + v1;
                s2 += v0 * v0 + v1 * v1;
            }
            s  += __shfl_xor_sync(0xffffffffu, s, 1);
            s2 += __shfl_xor_sync(0xffffffffu, s2, 1);
            s  += __shfl_xor_sync(0xffffffffu, s, 2);
            s2 += __shfl_xor_sync(0xffffffffu, s2, 2);
            if (q == 0) {
                red[wn * 64 + wm * 32 + mf * 16 + h * 8 + g]  = s;
                red2[wn * 64 + wm * 32 + mf * 16 + h * 8 + g] = s2;
            }
        }
        __syncthreads();
        #pragma unroll
        for (int mf = 0; mf < 2; mf++)
        #pragma unroll
        for (int h = 0; h < 2; h++) {
            int r = wm * 32 + mf * 16 + h * 8 + g;
            float mean = (red[r] + red[64 + r] + red[128 + r] + red[192 + r]) * (1.f / 128.f);
            float ex2  = (red2[r] + red2[64 + r] + red2[128 + r] + red2[192 + r]) * (1.f / 128.f);
            float rstd = rsqrtf(fmaxf(ex2 - mean * mean, 0.f) + 1e-5f);
            #pragma unroll
            for (int nf = 0; nf < 4; nf++) {
                int cl = wn * 32 + nf * 8 + q * 2;
                float o0 = (accNE[mf][nf][h*2]   - mean) * rstd * gneS[cl]   + bneS[cl];
                float o1 = (accNE[mf][nf][h*2+1] - mean) * rstd * gneS[cl+1] + bneS[cl+1];
                // he -> A region, MMA layout (e-tile is dead now)
                *(uint32_t*)(sm + R_A + (uint32_t)r * PITCH + (uint32_t)cl * 2) = pkf2(o0, o1);
            }
        }
    }
    __syncthreads();   // he visible to all warps before FF ktiles

    // =================== FF phase (A = he, C = h1 chunks) ===================
    float accH2[2][4][4] = {};

    #pragma unroll 1
    for (int p = 0; p < 4; p++) {
        const int i0 = 5 + p * 2;
        // ---- tile i0 (we1[p]): h1 = relu(he@we1 + be1) -> bf16 into C
        {
            float acc[2][4][4] = {};
            compute_ktile(acc, aB, Bb[i0 & 1], wm, wn, lane);
            #pragma unroll
            for (int mf = 0; mf < 2; mf++)
            #pragma unroll
            for (int h = 0; h < 2; h++) {
                int r = wm * 32 + mf * 16 + h * 8 + g;
                #pragma unroll
                for (int nf = 0; nf < 4; nf++) {
                    int cl = wn * 32 + nf * 8 + q * 2;
                    int cgl = p * 128 + cl;
                    float o0 = fmaxf(acc[mf][nf][h*2]   + be1S[cgl],   0.f);
                    float o1 = fmaxf(acc[mf][nf][h*2+1] + be1S[cgl+1], 0.f);
                    *(uint32_t*)(sm + R_C + (uint32_t)r * PITCH + (uint32_t)cl * 2) = pkf2(o0, o1);
                }
            }
        }
        CP_WAIT0(); __syncthreads();
        if (i0 + 2 < 13) prefetch_w(Bb[i0 & 1], tiles[i0 + 2], tid);
        // ---- tile i0+1 (we2[p]): h2 += h1chunk @ we2
        compute_ktile(accH2, cB, Bb[(i0 + 1) & 1], wm, wn, lane);
        if (p < 3) {                         // final iteration: no reuse, skip barrier
            CP_WAIT0(); __syncthreads();
            prefetch_w(Bb[(i0 + 1) & 1], tiles[i0 + 3], tid);
        }
    }

    // ---- FF epilogue: e_out = LN(e + h2 + be2) * gne + bne (single-pass LN)
    #pragma unroll
    for (int mf = 0; mf < 2; mf++)
    #pragma unroll
    for (int h = 0; h < 2; h++) {
        int r = wm * 32 + mf * 16 + h * 8 + g;
        #pragma unroll
        for (int nf = 0; nf < 4; nf++) {
            int cl = wn * 32 + nf * 8 + q * 2;
            float2 ev = *(const float2*)(e + (row0 + r) * ED_ + cl);
            accH2[mf][nf][h*2+0] += be2S[cl]   + ev.x;
            accH2[mf][nf][h*2+1] += be2S[cl+1] + ev.y;
        }
    }
    #pragma unroll
    for (int mf = 0; mf < 2; mf++)
    #pragma unroll
    for (int h = 0; h < 2; h++) {
        float s = 0.f, s2 = 0.f;
        #pragma unroll
        for (int nf = 0; nf < 4; nf++) {
            float v0 = accH2[mf][nf][h*2], v1 = accH2[mf][nf][h*2+1];
            s += v0 + v1;
            s2 += v0 * v0 + v1 * v1;
        }
        s  += __shfl_xor_sync(0xffffffffu, s, 1);
        s2 += __shfl_xor_sync(0xffffffffu, s2, 1);
        s  += __shfl_xor_sync(0xffffffffu, s, 2);
        s2 += __shfl_xor_sync(0xffffffffu, s2, 2);
        if (q == 0) {
            red[wn * 64 + wm * 32 + mf * 16 + h * 8 + g]  = s;
            red2[wn * 64 + wm * 32 + mf * 16 + h * 8 + g] = s2;
        }
    }
    __syncthreads();
    #pragma unroll
    for (int mf = 0; mf < 2; mf++)
    #pragma unroll
    for (int h = 0; h < 2; h++) {
        int r = wm * 32 + mf * 16 + h * 8 + g;
        float mean = (red[r] + red[64 + r] + red[128 + r] + red[192 + r]) * (1.f / 128.f);
        float ex2  = (red2[r] + red2[64 + r] + red2[128 + r] + red2[192 + r]) * (1.f / 128.f);
        float rstd = rsqrtf(fmaxf(ex2 - mean * mean, 0.f) + 1e-5f);
        #pragma unroll
        for (int nf = 0; nf < 4; nf++) {
            int cl = wn * 32 + nf * 8 + q * 2;
            float o0 = (accH2[mf][nf][h*2]   - mean) * rstd * gneS[cl]   + bneS[cl];
            float o1 = (accH2[mf][nf][h*2+1] - mean) * rstd * gneS[cl+1] + bneS[cl+1];
            *(float2*)(e_out + (row0 + r) * ED_ + cl) = make_float2(o0, o1);
        }
    }
}

// ---------------- node-side SIMT GEMM + LN ----------------
template<bool RELU>
__global__ void __launch_bounds__(256) gemm_kernel(
    const float* __restrict__ A, const float* __restrict__ W,
    const float* __restrict__ bias, float* __restrict__ C,
    int M, int N, int K, float alpha)
{
    __shared__ __align__(16) float aS[64][68];
    __shared__ __align__(16) float wS[64][68];
    const int tid = threadIdx.x;
    const int tx  = tid & 15;
    const int ty  = tid >> 4;
    const size_t row0 = (size_t)blockIdx.y * 64;
    const int    col0 = blockIdx.x * 64;
    float acc[4][4] = {};
    for (int k0 = 0; k0 < K; k0 += 64) {
        #pragma unroll
        for (int t = tid; t < 1024; t += 256) {
            int r = t >> 4, c4 = (t & 15) << 2;
            float4 av = *(const float4*)(A + (row0 + r) * K + k0 + c4);
            aS[r][c4+0]=av.x; aS[r][c4+1]=av.y; aS[r][c4+2]=av.z; aS[r][c4+3]=av.w;
            float4 wv = *(const float4*)(W + (size_t)(k0 + r) * N + col0 + c4);
            wS[r][c4+0]=wv.x; wS[r][c4+1]=wv.y; wS[r][c4+2]=wv.z; wS[r][c4+3]=wv.w;
        }
        __syncthreads();
        #pragma unroll 16
        for (int k = 0; k < 64; ++k) {
            float a0=aS[ty*4+0][k], a1=aS[ty*4+1][k], a2=aS[ty*4+2][k], a3=aS[ty*4+3][k];
            float4 bv = *(const float4*)&wS[k][tx*4];
            acc[0][0]+=a0*bv.x; acc[0][1]+=a0*bv.y; acc[0][2]+=a0*bv.z; acc[0][3]+=a0*bv.w;
            acc[1][0]+=a1*bv.x; acc[1][1]+=a1*bv.y; acc[1][2]+=a1*bv.z; acc[1][3]+=a1*bv.w;
            acc[2][0]+=a2*bv.x; acc[2][1]+=a2*bv.y; acc[2][2]+=a2*bv.z; acc[2][3]+=a2*bv.w;
            acc[3][0]+=a3*bv.x; acc[3][1]+=a3*bv.y; acc[3][2]+=a3*bv.z; acc[3][3]+=a3*bv.w;
        }
        __syncthreads();
    }
    const int c = col0 + tx * 4;
    float b0=bias[c+0], b1=bias[c+1], b2=bias[c+2], b3=bias[c+3];
    #pragma unroll
    for (int m = 0; m < 4; ++m) {
        float4 o;
        o.x = alpha*(acc[m][0]+b0); o.y = alpha*(acc[m][1]+b1);
        o.z = alpha*(acc[m][2]+b2); o.w = alpha*(acc[m][3]+b3);
        if (RELU) { o.x=fmaxf(o.x,0.f); o.y=fmaxf(o.y,0.f); o.z=fmaxf(o.z,0.f); o.w=fmaxf(o.w,0.f); }
        *(float4*)(C + (row0 + ty*4 + m) * N + c) = o;
    }
}

__global__ void ln_kernel(const float* __restrict__ A, const float* __restrict__ Bv,
                          const float* __restrict__ g, const float* __restrict__ be,
                          float* __restrict__ out)
{
    __shared__ float red[8];
    const int D = blockDim.x;
    const size_t base = (size_t)blockIdx.x * D + threadIdx.x;
    const int lane = threadIdx.x & 31;
    const int w    = threadIdx.x >> 5;
    const int nw   = D >> 5;
    float v = A[base] + Bv[base];
    float s = v;
    #pragma unroll
    for (int o = 16; o; o >>= 1) s += __shfl_xor_sync(0xffffffffu, s, o);
    if (lane == 0) red[w] = s;
    __syncthreads();
    float tot = 0.f;
    for (int ww = 0; ww < nw; ++ww) tot += red[ww];
    float mean = tot / (float)D;
    float d = v - mean;
    __syncthreads();
    float s2 = d * d;
    #pragma unroll
    for (int o = 16; o; o >>= 1) s2 += __shfl_xor_sync(0xffffffffu, s2, o);
    if (lane == 0) red[w] = s2;
    __syncthreads();
    float tot2 = 0.f;
    for (int ww = 0; ww < nw; ++ww) tot2 += red[ww];
    float var = tot2 / (float)D;
    out[base] = d * rsqrtf(var + 1e-5f) * g[threadIdx.x] + be[threadIdx.x];
}

// ---------------- launcher ----------------
extern "C" void kernel_launch(void* const* d_in, const int* in_sizes, int n_in,
                              void* d_out, int out_size)
{
    const float* x   = (const float*)d_in[0];
    const float* e   = (const float*)d_in[1];
    const float* wq  = (const float*)d_in[2];
    const float* wk  = (const float*)d_in[3];
    const float* wv  = (const float*)d_in[4];
    const float* wem = (const float*)d_in[5];
    const float* wea = (const float*)d_in[6];
    const float* wxo = (const float*)d_in[7];
    const float* weo = (const float*)d_in[8];
    const float* wx1 = (const float*)d_in[9];
    const float* wx2 = (const float*)d_in[10];
    const float* we1 = (const float*)d_in[11];
    const float* we2 = (const float*)d_in[12];
    const float* bq  = (const float*)d_in[13];
    const float* bk  = (const float*)d_in[14];
    const float* bv  = (const float*)d_in[15];
    const float* bem = (const float*)d_in[16];
    const float* bea = (const float*)d_in[17];
    const float* bxo = (const float*)d_in[18];
    const float* beo = (const float*)d_in[19];
    const float* bx1 = (const float*)d_in[20];
    const float* bx2 = (const float*)d_in[21];
    const float* be1 = (const float*)d_in[22];
    const float* be2 = (const float*)d_in[23];
    const float* gnx = (const float*)d_in[24];
    const float* bnx = (const float*)d_in[25];
    const float* gne = (const float*)d_in[26];
    const float* bne = (const float*)d_in[27];

    float* x_out = (float*)d_out;
    float* e_out = (float*)d_out + (size_t)ROWS_X * XD_;

    float *Q, *Km, *newX, *hx, *h1x, *h2x, *wvx, *bvx, *zero, *w2, *beoF;
    char *wemP, *weoP, *w2P, *we1P, *we2P;
    cudaGetSymbolAddress((void**)&Q,    g_Q);
    cudaGetSymbolAddress((void**)&Km,   g_Km);
    cudaGetSymbolAddress((void**)&newX, g_newX);
    cudaGetSymbolAddress((void**)&hx,   g_hx);
    cudaGetSymbolAddress((void**)&h1x,  g_h1x);
    cudaGetSymbolAddress((void**)&h2x,  g_h2x);
    cudaGetSymbolAddress((void**)&wvx,  g_wvx);
    cudaGetSymbolAddress((void**)&bvx,  g_bvx);
    cudaGetSymbolAddress((void**)&zero, g_zero);
    cudaGetSymbolAddress((void**)&w2,   g_w2);
    cudaGetSymbolAddress((void**)&beoF, g_beoF);
    cudaGetSymbolAddress((void**)&wemP, g_wemP);
    cudaGetSymbolAddress((void**)&weoP, g_weoP);
    cudaGetSymbolAddress((void**)&w2P,  g_w2P);
    cudaGetSymbolAddress((void**)&we1P, g_we1P);
    cudaGetSymbolAddress((void**)&we2P, g_we2P);

    cudaFuncSetAttribute(edge_fused_kernel, cudaFuncAttributeMaxDynamicSharedMemorySize, EF_BYTES);
    cudaFuncSetAttribute(prep_all12,        cudaFuncAttributeMaxDynamicSharedMemorySize, 128 * 129 * 4);
    cudaFuncSetAttribute(prep_w2,           cudaFuncAttributeMaxDynamicSharedMemorySize, 128 * 129 * 4);

    // one-time side-stream/event setup (host objects only)
    static cudaStream_t sNode = nullptr, sQK = nullptr, sW2 = nullptr;
    static cudaEvent_t evFork = nullptr, evJoin = nullptr, evQK = nullptr, evW2 = nullptr;
    if (!sNode) {
        cudaStreamCreateWithFlags(&sNode, cudaStreamNonBlocking);
        cudaStreamCreateWithFlags(&sQK,   cudaStreamNonBlocking);
        cudaStreamCreateWithFlags(&sW2,   cudaStreamNonBlocking);
        cudaEventCreateWithFlags(&evFork, cudaEventDisableTiming);
        cudaEventCreateWithFlags(&evJoin, cudaEventDisableTiming);
        cudaEventCreateWithFlags(&evQK,   cudaEventDisableTiming);
        cudaEventCreateWithFlags(&evW2,   cudaEventDisableTiming);
    }

    dim3 blk(256);
    auto grid_of = [](int M, int N) { return dim3((unsigned)(N/64), (unsigned)(M/64)); };

    // ---- fork ----
    cudaEventRecord(evFork, 0);
    cudaStreamWaitEvent(sNode, evFork, 0);
    cudaStreamWaitEvent(sQK,   evFork, 0);
    cudaStreamWaitEvent(sW2,   evFork, 0);

    // node side on sNode (softmax collapses: wV == V; fold wv@wxo)
    gemm_kernel<false><<<grid_of(XD_, XD_), blk, 0, sNode>>>(wv, wxo, zero, wvx, XD_, XD_, XD_, 1.f);
    fold_bias<<<1, 256, 0, sNode>>>(bv, wxo, bxo, bvx);
    gemm_kernel<false><<<grid_of(ROWS_X, XD_), blk, 0, sNode>>>(x, wvx, bvx, newX, ROWS_X, XD_, XD_, 1.f);
    ln_kernel<<<ROWS_X, XD_, 0, sNode>>>(x, newX, gnx, bnx, hx);
    gemm_kernel<true ><<<grid_of(ROWS_X, FFX), blk, 0, sNode>>>(hx,  wx1, bx1, h1x, ROWS_X, FFX, XD_, 1.f);
    gemm_kernel<false><<<grid_of(ROWS_X, XD_), blk, 0, sNode>>>(h1x, wx2, bx2, h2x, ROWS_X, XD_, FFX, 1.f);
    ln_kernel<<<ROWS_X, XD_, 0, sNode>>>(x, h2x, gnx, bnx, x_out);
    cudaEventRecord(evJoin, sNode);

    // Q/K projections on sQK
    gemm_kernel<false><<<grid_of(ROWS_X, XD_), blk, 0, sQK>>>(x, wq, bq, Q,  ROWS_X, XD_, XD_, INV_SQRT_DF);
    gemm_kernel<false><<<grid_of(ROWS_X, XD_), blk, 0, sQK>>>(x, wk, bk, Km, ROWS_X, XD_, XD_, 1.f);
    cudaEventRecord(evQK, sQK);

    // W2 chain on sW2: W2 = wea@weo -> fold_beo -> prep w2 tile
    gemm_kernel<false><<<grid_of(ED_, ED_), blk, 0, sW2>>>(wea, weo, zero, w2, ED_, ED_, XD_, 1.f);
    fold_beo<<<1, 128, 0, sW2>>>(bea, weo, beo, beoF);
    prep_w2<<<1, 256, 128 * 129 * 4, sW2>>>(w2, w2P);
    cudaEventRecord(evW2, sW2);

    // main stream: prep of the 12 direct weight tiles, then edge
    prep_all12<<<12, 256, 128 * 129 * 4>>>(wem, weo, we1, we2, wemP, weoP, we1P, we2P);
    cudaStreamWaitEvent(0, evQK, 0);
    cudaStreamWaitEvent(0, evW2, 0);

    edge_fused_kernel<<<ROWS_E / 64, blk, EF_BYTES>>>(
        e, Q, Km, w2P, wemP, weoP, we1P, we2P,
        bem, beoF, be1, be2, gne, bne, e_out);

    // ---- join ----
    cudaStreamWaitEvent(0, evJoin, 0);
}